// round 1
// baseline (speedup 1.0000x reference)
#include <cuda_runtime.h>
#include <math_constants.h>

// Problem constants
#define BB   8
#define TT   1024
#define CC   768
#define HH   12
#define HD   64
#define MM   (BB * TT)       // 8192
#define N3   (3 * CC)        // 2304

// Scratch (static device globals: allowed; no runtime allocation)
__device__ float g_q[BB * HH * TT * HD];
__device__ float g_k[BB * HH * TT * HD];
__device__ float g_v[BB * HH * TT * HD];
__device__ float g_y[MM * CC];

// ---------------------------------------------------------------------------
// Kernel 1: QKV GEMM.  X[8192,768] @ W[768,2304] + b -> scatter to q/k/v
// laid out as [B, H, T, hd].
// Tiling: 128x128 C-tile, BK=16, 256 threads, 8x8 per-thread microtile.
// ---------------------------------------------------------------------------
__global__ __launch_bounds__(256) void qkv_gemm(const float* __restrict__ X,
                                                const float* __restrict__ W,
                                                const float* __restrict__ bias)
{
    __shared__ float As[16][132];  // A stored transposed: As[k][m]
    __shared__ float Bs[16][132];  // Bs[k][n]

    const int tid = threadIdx.x;
    const int ty  = tid >> 4;      // 0..15
    const int tx  = tid & 15;      // 0..15
    const int m0  = blockIdx.y * 128;
    const int n0  = blockIdx.x * 128;

    float acc[8][8];
#pragma unroll
    for (int i = 0; i < 8; i++)
#pragma unroll
        for (int j = 0; j < 8; j++) acc[i][j] = 0.f;

    const int ar = tid >> 2;         // 0..63
    const int ac = (tid & 3) * 4;    // 0,4,8,12
    const int br = tid >> 5;         // 0..7
    const int bc = (tid & 31) * 4;   // 0..124

    for (int k0 = 0; k0 < CC; k0 += 16) {
#pragma unroll
        for (int i = 0; i < 2; i++) {
            float4 av = *(const float4*)(X + (size_t)(m0 + ar + i * 64) * CC + k0 + ac);
            As[ac + 0][ar + i * 64] = av.x;
            As[ac + 1][ar + i * 64] = av.y;
            As[ac + 2][ar + i * 64] = av.z;
            As[ac + 3][ar + i * 64] = av.w;
        }
#pragma unroll
        for (int i = 0; i < 2; i++) {
            float4 bv = *(const float4*)(W + (size_t)(k0 + br + i * 8) * N3 + n0 + bc);
            *(float4*)&Bs[br + i * 8][bc] = bv;
        }
        __syncthreads();

#pragma unroll
        for (int kk = 0; kk < 16; kk++) {
            float4 a0 = *(float4*)&As[kk][ty * 8];
            float4 a1 = *(float4*)&As[kk][ty * 8 + 4];
            float4 b0 = *(float4*)&Bs[kk][tx * 8];
            float4 b1 = *(float4*)&Bs[kk][tx * 8 + 4];
            float a[8] = {a0.x, a0.y, a0.z, a0.w, a1.x, a1.y, a1.z, a1.w};
            float b[8] = {b0.x, b0.y, b0.z, b0.w, b1.x, b1.y, b1.z, b1.w};
#pragma unroll
            for (int i = 0; i < 8; i++)
#pragma unroll
                for (int j = 0; j < 8; j++) acc[i][j] += a[i] * b[j];
        }
        __syncthreads();
    }

    // Epilogue: bias + scatter.  Entire 128-col tile lies in one of q/k/v.
    const int which = n0 / CC;                 // 0=q, 1=k, 2=v
    float* dst = (which == 0) ? g_q : (which == 1) ? g_k : g_v;
#pragma unroll
    for (int i = 0; i < 8; i++) {
        const int m  = m0 + ty * 8 + i;
        const int b_ = m >> 10;
        const int t  = m & 1023;
#pragma unroll
        for (int j = 0; j < 8; j++) {
            const int n = n0 + tx * 8 + j;
            const int c = n - which * CC;
            const int h = c >> 6;
            const int d = c & 63;
            dst[(size_t)((b_ * HH + h) * TT + t) * HD + d] = acc[i][j] + bias[n];
        }
    }
}

// ---------------------------------------------------------------------------
// Kernel 2: causal flash attention.
// Block: one (b,h) pair + one 64-row Q tile. 256 threads, 4x4 microtiles.
// Online softmax; K tiles beyond the causal frontier skipped entirely.
// ---------------------------------------------------------------------------
#define ATTN_SMEM_FLOATS (2 * 64 * 65 + 2 * 64 * 68 + 64 * 16 + 3 * 64)

__global__ __launch_bounds__(256) void attn_kernel()
{
    extern __shared__ float sm[];
    float* Qt  = sm;                 // [64][65], transposed: Qt[d][row]
    float* Pt  = Qt + 64 * 65;       // [64][65], transposed: Pt[kcol][row]
    float* Kt  = Pt + 64 * 65;       // [64][68], transposed: Kt[d][kcol]
    float* Vs  = Kt + 64 * 68;       // [64][68], natural:    Vs[krow][d]
    float* red = Vs + 64 * 68;       // [64][16]
    float* m_s = red + 64 * 16;      // [64]
    float* l_s = m_s + 64;           // [64]
    float* fac = l_s + 64;           // [64]

    const int tid = threadIdx.x;
    const int ty  = tid >> 4, tx = tid & 15;
    const int r0  = ty * 4, c0 = tx * 4;
    const int qt  = blockIdx.x;       // 0..15
    const int bh  = blockIdx.y;       // 0..95
    const int q0  = qt * 64;

    const float* Qg = g_q + (size_t)(bh * TT + q0) * HD;
    const float* Kg = g_k + (size_t)bh * TT * HD;
    const float* Vg = g_v + (size_t)bh * TT * HD;

    // Load Q tile transposed, pre-scaled by 1/sqrt(hd)
#pragma unroll
    for (int i = 0; i < 16; i++) {
        int idx = tid + i * 256;
        int row = idx >> 6, d = idx & 63;
        Qt[d * 65 + row] = Qg[row * 64 + d] * 0.125f;
    }
    if (tid < 64) { m_s[tid] = -CUDART_INF_F; l_s[tid] = 0.f; }
    __syncthreads();

    float o[4][4] = {};

    for (int kt = 0; kt <= qt; kt++) {
        const int k0 = kt * 64;
        // Load K (transposed) and V tiles
#pragma unroll
        for (int i = 0; i < 16; i++) {
            int idx = tid + i * 256;
            int row = idx >> 6, d = idx & 63;
            Kt[d * 68 + row] = Kg[(size_t)(k0 + row) * 64 + d];
            Vs[row * 68 + d] = Vg[(size_t)(k0 + row) * 64 + d];
        }
        __syncthreads();

        // S = Q @ K^T (4x4 per thread)
        float s[4][4] = {};
#pragma unroll 16
        for (int d = 0; d < 64; d++) {
            float qv[4];
#pragma unroll
            for (int rr = 0; rr < 4; rr++) qv[rr] = Qt[d * 65 + r0 + rr];
            float4 kv = *(float4*)&Kt[d * 68 + c0];
#pragma unroll
            for (int rr = 0; rr < 4; rr++) {
                s[rr][0] += qv[rr] * kv.x;
                s[rr][1] += qv[rr] * kv.y;
                s[rr][2] += qv[rr] * kv.z;
                s[rr][3] += qv[rr] * kv.w;
            }
        }

        if (kt == qt) {  // causal mask on the diagonal tile
#pragma unroll
            for (int rr = 0; rr < 4; rr++)
#pragma unroll
                for (int cc = 0; cc < 4; cc++)
                    if (c0 + cc > r0 + rr) s[rr][cc] = -CUDART_INF_F;
        }

        // Row max (partial per thread -> smem -> 64-thread reduce)
#pragma unroll
        for (int rr = 0; rr < 4; rr++) {
            float rm = fmaxf(fmaxf(s[rr][0], s[rr][1]), fmaxf(s[rr][2], s[rr][3]));
            red[(r0 + rr) * 16 + tx] = rm;
        }
        __syncthreads();
        if (tid < 64) {
            float mt = red[tid * 16];
#pragma unroll
            for (int j = 1; j < 16; j++) mt = fmaxf(mt, red[tid * 16 + j]);
            float mo = m_s[tid];
            float mn = fmaxf(mo, mt);
            fac[tid] = __expf(mo - mn);
            m_s[tid] = mn;
        }
        __syncthreads();

        // P = exp(S - m_new), write transposed to smem; partial row sums
#pragma unroll
        for (int rr = 0; rr < 4; rr++) {
            float mn = m_s[r0 + rr];
            float rs = 0.f;
#pragma unroll
            for (int cc = 0; cc < 4; cc++) {
                float p = __expf(s[rr][cc] - mn);
                Pt[(c0 + cc) * 65 + r0 + rr] = p;
                rs += p;
            }
            red[(r0 + rr) * 16 + tx] = rs;
        }
        __syncthreads();
        if (tid < 64) {
            float ls = 0.f;
#pragma unroll
            for (int j = 0; j < 16; j++) ls += red[tid * 16 + j];
            l_s[tid] = l_s[tid] * fac[tid] + ls;
        }

        // Rescale O, then O += P @ V
#pragma unroll
        for (int rr = 0; rr < 4; rr++) {
            float f = fac[r0 + rr];
#pragma unroll
            for (int cc = 0; cc < 4; cc++) o[rr][cc] *= f;
        }
#pragma unroll 16
        for (int kk = 0; kk < 64; kk++) {
            float pv[4];
#pragma unroll
            for (int rr = 0; rr < 4; rr++) pv[rr] = Pt[kk * 65 + r0 + rr];
            float4 vv = *(float4*)&Vs[kk * 68 + c0];
#pragma unroll
            for (int rr = 0; rr < 4; rr++) {
                o[rr][0] += pv[rr] * vv.x;
                o[rr][1] += pv[rr] * vv.y;
                o[rr][2] += pv[rr] * vv.z;
                o[rr][3] += pv[rr] * vv.w;
            }
        }
        __syncthreads();
    }

    // Final normalize and write y in [B, T, C] (C = h*64 + d)
    const int b = bh / HH, h = bh % HH;
#pragma unroll
    for (int rr = 0; rr < 4; rr++) {
        float inv = 1.f / l_s[r0 + rr];
        size_t base = (size_t)((b * TT) + q0 + r0 + rr) * CC + h * HD + c0;
#pragma unroll
        for (int cc = 0; cc < 4; cc++)
            g_y[base + cc] = o[rr][cc] * inv;
    }
}

// ---------------------------------------------------------------------------
// Kernel 3: output projection.  y[8192,768] @ Wp[768,768] + bp -> out
// ---------------------------------------------------------------------------
__global__ __launch_bounds__(256) void proj_gemm(const float* __restrict__ W,
                                                 const float* __restrict__ bias,
                                                 float* __restrict__ out)
{
    __shared__ float As[16][132];
    __shared__ float Bs[16][132];

    const int tid = threadIdx.x;
    const int ty  = tid >> 4, tx = tid & 15;
    const int m0  = blockIdx.y * 128;
    const int n0  = blockIdx.x * 128;

    float acc[8][8];
#pragma unroll
    for (int i = 0; i < 8; i++)
#pragma unroll
        for (int j = 0; j < 8; j++) acc[i][j] = 0.f;

    const int ar = tid >> 2, ac = (tid & 3) * 4;
    const int br = tid >> 5, bc = (tid & 31) * 4;

    for (int k0 = 0; k0 < CC; k0 += 16) {
#pragma unroll
        for (int i = 0; i < 2; i++) {
            float4 av = *(const float4*)(g_y + (size_t)(m0 + ar + i * 64) * CC + k0 + ac);
            As[ac + 0][ar + i * 64] = av.x;
            As[ac + 1][ar + i * 64] = av.y;
            As[ac + 2][ar + i * 64] = av.z;
            As[ac + 3][ar + i * 64] = av.w;
        }
#pragma unroll
        for (int i = 0; i < 2; i++) {
            float4 bv = *(const float4*)(W + (size_t)(k0 + br + i * 8) * CC + n0 + bc);
            *(float4*)&Bs[br + i * 8][bc] = bv;
        }
        __syncthreads();

#pragma unroll
        for (int kk = 0; kk < 16; kk++) {
            float4 a0 = *(float4*)&As[kk][ty * 8];
            float4 a1 = *(float4*)&As[kk][ty * 8 + 4];
            float4 b0 = *(float4*)&Bs[kk][tx * 8];
            float4 b1 = *(float4*)&Bs[kk][tx * 8 + 4];
            float a[8] = {a0.x, a0.y, a0.z, a0.w, a1.x, a1.y, a1.z, a1.w};
            float b[8] = {b0.x, b0.y, b0.z, b0.w, b1.x, b1.y, b1.z, b1.w};
#pragma unroll
            for (int i = 0; i < 8; i++)
#pragma unroll
                for (int j = 0; j < 8; j++) acc[i][j] += a[i] * b[j];
        }
        __syncthreads();
    }

#pragma unroll
    for (int i = 0; i < 8; i++) {
        const int m = m0 + ty * 8 + i;
#pragma unroll
        for (int j = 0; j < 8; j++) {
            const int n = n0 + tx * 8 + j;
            out[(size_t)m * CC + n] = acc[i][j] + bias[n];
        }
    }
}

// ---------------------------------------------------------------------------
extern "C" void kernel_launch(void* const* d_in, const int* in_sizes, int n_in,
                              void* d_out, int out_size)
{
    const float* x      = (const float*)d_in[0];
    const float* W_attn = (const float*)d_in[1];
    const float* b_attn = (const float*)d_in[2];
    const float* W_proj = (const float*)d_in[3];
    const float* b_proj = (const float*)d_in[4];
    float* out = (float*)d_out;

    static_assert(ATTN_SMEM_FLOATS * 4 == 72960, "smem size");
    cudaFuncSetAttribute(attn_kernel,
                         cudaFuncAttributeMaxDynamicSharedMemorySize,
                         ATTN_SMEM_FLOATS * 4);

    {
        dim3 grid(N3 / 128, MM / 128);   // (18, 64)
        qkv_gemm<<<grid, 256>>>(x, W_attn, b_attn);
    }
    {
        dim3 grid(TT / 64, BB * HH);     // (16, 96)
        attn_kernel<<<grid, 256, ATTN_SMEM_FLOATS * 4>>>();
    }
    {
        dim3 grid(CC / 128, MM / 128);   // (6, 64)
        proj_gemm<<<grid, 256>>>(W_proj, b_proj, out);
    }
}

// round 6
// speedup vs baseline: 1.7871x; 1.7871x over previous
#include <cuda_runtime.h>
#include <cuda_bf16.h>
#include <math_constants.h>
#include <cstdint>

#define BB   8
#define TT   1024
#define CC   768
#define HH   12
#define HD   64
#define MM   (BB * TT)       // 8192
#define N3   (3 * CC)        // 2304

// ---------------------------------------------------------------------------
// Static device scratch (referenced ONLY from device code — host code must
// never take these symbols' addresses)
// ---------------------------------------------------------------------------
__device__ __align__(16) float g_q[BB * HH * TT * HD];
__device__ __align__(16) float g_k[BB * HH * TT * HD];
__device__ __align__(16) float g_v[BB * HH * TT * HD];

__device__ __align__(16) __nv_bfloat16 g_xhi[MM * CC];
__device__ __align__(16) __nv_bfloat16 g_xlo[MM * CC];
__device__ __align__(16) __nv_bfloat16 g_wah[N3 * CC];   // W_attn^T [N3][CC] hi
__device__ __align__(16) __nv_bfloat16 g_wal[N3 * CC];
__device__ __align__(16) __nv_bfloat16 g_wph[CC * CC];   // W_proj^T hi
__device__ __align__(16) __nv_bfloat16 g_wpl[CC * CC];
__device__ __align__(16) __nv_bfloat16 g_yhi[MM * CC];
__device__ __align__(16) __nv_bfloat16 g_ylo[MM * CC];

// ---------------------------------------------------------------------------
// PTX helpers
// ---------------------------------------------------------------------------
__device__ __forceinline__ uint32_t smem_u32(const void* p) {
    uint32_t a;
    asm("{ .reg .u64 t; cvta.to.shared.u64 t, %1; cvt.u32.u64 %0, t; }" : "=r"(a) : "l"(p));
    return a;
}
__device__ __forceinline__ void mma_bf16(float* d, const uint32_t* a, const uint32_t* b,
                                         const float* c) {
    asm volatile("mma.sync.aligned.m16n8k16.row.col.f32.bf16.bf16.f32 "
                 "{%0,%1,%2,%3}, {%4,%5,%6,%7}, {%8,%9}, {%10,%11,%12,%13};"
                 : "=f"(d[0]), "=f"(d[1]), "=f"(d[2]), "=f"(d[3])
                 : "r"(a[0]), "r"(a[1]), "r"(a[2]), "r"(a[3]), "r"(b[0]), "r"(b[1]),
                   "f"(c[0]), "f"(c[1]), "f"(c[2]), "f"(c[3]));
}
__device__ __forceinline__ void cp16(uint32_t dst, const void* src) {
    asm volatile("cp.async.cg.shared.global [%0], [%1], 16;" :: "r"(dst), "l"(src));
}
__device__ __forceinline__ void cp_commit() {
    asm volatile("cp.async.commit_group;" ::: "memory");
}
template <int N>
__device__ __forceinline__ void cp_wait() {
    asm volatile("cp.async.wait_group %0;" :: "n"(N) : "memory");
}

// ---------------------------------------------------------------------------
// HMMA GEMM: C[128x128] += A[M,K] x B^T, split-bf16 3-pass.
// Smem stage: 4 tiles (Ah, Al, Bh, Bl), each 128 rows x 32 bf16, pitch 80 B.
// Two stages, cp.async double-buffered. Fragments via explicit per-lane LDS.
// ---------------------------------------------------------------------------
#define ROWB      80
#define TILE_B    (128 * ROWB)          // 10240 bytes
#define STAGE_B   (4 * TILE_B)          // 40960
#define GEMM_SMEM (2 * STAGE_B)         // 81920
#define NITER     (CC / 32)             // 24

__device__ __forceinline__ void load_stage(const __nv_bfloat16* Ah, const __nv_bfloat16* Al,
                                           const __nv_bfloat16* Bh, const __nv_bfloat16* Bl,
                                           int m0, int n0, int k0,
                                           uint32_t sbase, int tid) {
    const __nv_bfloat16* srcs[4] = {Ah + (size_t)m0 * CC, Al + (size_t)m0 * CC,
                                    Bh + (size_t)n0 * CC, Bl + (size_t)n0 * CC};
#pragma unroll
    for (int i = 0; i < 8; i++) {
        int e = tid + i * 256;            // 0..2047
        int t = e >> 9;                   // tile 0..3
        int idx = e & 511;
        int row = idx >> 2, c = idx & 3;  // 4 x 16B per row
        cp16(sbase + t * TILE_B + row * ROWB + c * 16,
             srcs[t] + (size_t)row * CC + k0 + c * 8);
    }
}

// Fragments per PTX ISA tables. g = lane>>2, q = lane&3.
// A regs: (g,2q),(g+8,2q),(g,2q+8),(g+8,2q+8) pairs; B regs: (n=g, k=2q / 2q+8).
__device__ __forceinline__ void gemm_compute(const char* stage, int lane, int wm, int wn,
                                             float acc[4][4][4]) {
    const char* sAh = stage;
    const char* sAl = stage + TILE_B;
    const char* sBh = stage + 2 * TILE_B;
    const char* sBl = stage + 3 * TILE_B;
    const int g = lane >> 2, q = lane & 3;

#pragma unroll
    for (int kk = 0; kk < 2; kk++) {
        const int kb = kk * 32 + q * 4;   // byte offset of k = kk*16 + 2q

        uint32_t bh[4][2], bl[4][2];
#pragma unroll
        for (int nj = 0; nj < 4; nj++) {
            const int nb = (wn + nj * 8 + g) * ROWB + kb;
            bh[nj][0] = *(const uint32_t*)(sBh + nb);
            bh[nj][1] = *(const uint32_t*)(sBh + nb + 16);
            bl[nj][0] = *(const uint32_t*)(sBl + nb);
            bl[nj][1] = *(const uint32_t*)(sBl + nb + 16);
        }
#pragma unroll
        for (int mi = 0; mi < 4; mi++) {
            const int ab = (wm + mi * 16 + g) * ROWB + kb;
            uint32_t ah[4], al[4];
            ah[0] = *(const uint32_t*)(sAh + ab);
            ah[1] = *(const uint32_t*)(sAh + ab + 8 * ROWB);
            ah[2] = *(const uint32_t*)(sAh + ab + 16);
            ah[3] = *(const uint32_t*)(sAh + ab + 8 * ROWB + 16);
            al[0] = *(const uint32_t*)(sAl + ab);
            al[1] = *(const uint32_t*)(sAl + ab + 8 * ROWB);
            al[2] = *(const uint32_t*)(sAl + ab + 16);
            al[3] = *(const uint32_t*)(sAl + ab + 8 * ROWB + 16);
#pragma unroll
            for (int nj = 0; nj < 4; nj++) {
                mma_bf16(acc[mi][nj], ah, bh[nj], acc[mi][nj]);
                mma_bf16(acc[mi][nj], ah, bl[nj], acc[mi][nj]);
                mma_bf16(acc[mi][nj], al, bh[nj], acc[mi][nj]);
            }
        }
    }
}

__device__ __forceinline__ void gemm_mainloop(const __nv_bfloat16* Ah, const __nv_bfloat16* Al,
                                              const __nv_bfloat16* Bh, const __nv_bfloat16* Bl,
                                              int m0, int n0, char* sm,
                                              int tid, int lane, int wm, int wn,
                                              float acc[4][4][4]) {
    const uint32_t sbase = smem_u32(sm);
    load_stage(Ah, Al, Bh, Bl, m0, n0, 0, sbase, tid);
    cp_commit();
    for (int c = 0; c < NITER; c++) {
        if (c + 1 < NITER) {
            load_stage(Ah, Al, Bh, Bl, m0, n0, (c + 1) * 32,
                       sbase + ((c + 1) & 1) * STAGE_B, tid);
            cp_commit();
            cp_wait<1>();
        } else {
            cp_wait<0>();
        }
        __syncthreads();
        gemm_compute(sm + (c & 1) * STAGE_B, lane, wm, wn, acc);
        __syncthreads();
    }
}

// ---------------------------------------------------------------------------
// QKV GEMM -> scatter into g_q/g_k/g_v [B,H,T,hd] with bias
// ---------------------------------------------------------------------------
__global__ __launch_bounds__(256, 2) void qkv_mm(const float* __restrict__ bias)
{
    extern __shared__ char sm[];
    const int tid = threadIdx.x, lane = tid & 31, wid = tid >> 5;
    const int wm = (wid & 1) * 64, wn = (wid >> 1) * 32;
    const int m0 = blockIdx.y * 128, n0 = blockIdx.x * 128;

    float acc[4][4][4];
#pragma unroll
    for (int a = 0; a < 4; a++)
#pragma unroll
        for (int b = 0; b < 4; b++)
#pragma unroll
            for (int c = 0; c < 4; c++) acc[a][b][c] = 0.f;

    gemm_mainloop(g_xhi, g_xlo, g_wah, g_wal, m0, n0, sm, tid, lane, wm, wn, acc);

    const int g = lane >> 2, t4 = lane & 3;
    const int which = blockIdx.x / 6;
    float* dst = (which == 0) ? g_q : (which == 1) ? g_k : g_v;
#pragma unroll
    for (int mi = 0; mi < 4; mi++) {
#pragma unroll
        for (int half = 0; half < 2; half++) {
            const int m = m0 + wm + mi * 16 + g + half * 8;
            const int b_ = m >> 10, t = m & 1023;
#pragma unroll
            for (int nj = 0; nj < 4; nj++) {
                const int n = n0 + wn + nj * 8 + t4 * 2;
                const int ccol = n - which * CC;
                const int h = ccol >> 6, d = ccol & 63;
                float2 v;
                v.x = acc[mi][nj][half * 2 + 0] + __ldg(bias + n);
                v.y = acc[mi][nj][half * 2 + 1] + __ldg(bias + n + 1);
                *(float2*)(dst + ((size_t)((b_ * HH + h) * TT + t)) * HD + d) = v;
            }
        }
    }
}

// ---------------------------------------------------------------------------
// Proj GEMM -> out fp32 [M][CC] with bias
// ---------------------------------------------------------------------------
__global__ __launch_bounds__(256, 2) void proj_mm(const float* __restrict__ bias,
                                                  float* __restrict__ out)
{
    extern __shared__ char sm[];
    const int tid = threadIdx.x, lane = tid & 31, wid = tid >> 5;
    const int wm = (wid & 1) * 64, wn = (wid >> 1) * 32;
    const int m0 = blockIdx.y * 128, n0 = blockIdx.x * 128;

    float acc[4][4][4];
#pragma unroll
    for (int a = 0; a < 4; a++)
#pragma unroll
        for (int b = 0; b < 4; b++)
#pragma unroll
            for (int c = 0; c < 4; c++) acc[a][b][c] = 0.f;

    gemm_mainloop(g_yhi, g_ylo, g_wph, g_wpl, m0, n0, sm, tid, lane, wm, wn, acc);

    const int g = lane >> 2, t4 = lane & 3;
#pragma unroll
    for (int mi = 0; mi < 4; mi++) {
#pragma unroll
        for (int half = 0; half < 2; half++) {
            const int m = m0 + wm + mi * 16 + g + half * 8;
#pragma unroll
            for (int nj = 0; nj < 4; nj++) {
                const int n = n0 + wn + nj * 8 + t4 * 2;
                float2 v;
                v.x = acc[mi][nj][half * 2 + 0] + __ldg(bias + n);
                v.y = acc[mi][nj][half * 2 + 1] + __ldg(bias + n + 1);
                *(float2*)(out + (size_t)m * CC + n) = v;
            }
        }
    }
}

// ---------------------------------------------------------------------------
// Conversion kernels — outputs are the device globals, referenced from
// DEVICE code (host-side symbol addresses are invalid on this platform).
// ---------------------------------------------------------------------------
__global__ void split_x_kernel(const float* __restrict__ src)
{
    int i = blockIdx.x * blockDim.x + threadIdx.x;
    if (i >= MM * CC / 4) return;
    float4 v = ((const float4*)src)[i];
    __nv_bfloat16 h0 = __float2bfloat16(v.x);
    __nv_bfloat16 h1 = __float2bfloat16(v.y);
    __nv_bfloat16 h2 = __float2bfloat16(v.z);
    __nv_bfloat16 h3 = __float2bfloat16(v.w);
    __nv_bfloat162* hp = (__nv_bfloat162*)g_xhi;
    __nv_bfloat162* lp = (__nv_bfloat162*)g_xlo;
    hp[i * 2 + 0] = __nv_bfloat162(h0, h1);
    hp[i * 2 + 1] = __nv_bfloat162(h2, h3);
    lp[i * 2 + 0] = __nv_bfloat162(__float2bfloat16(v.x - __bfloat162float(h0)),
                                   __float2bfloat16(v.y - __bfloat162float(h1)));
    lp[i * 2 + 1] = __nv_bfloat162(__float2bfloat16(v.z - __bfloat162float(h2)),
                                   __float2bfloat16(v.w - __bfloat162float(h3)));
}

// W[K=CC][N] -> globals T[N][K] hi/lo.  sel: 0 = W_attn (N=N3), 1 = W_proj (N=CC)
__global__ void transpose_split_kernel(const float* __restrict__ W, int sel)
{
    __shared__ float tile[32][33];
    const int N = sel ? CC : N3;
    __nv_bfloat16* Th = sel ? g_wph : g_wah;
    __nv_bfloat16* Tl = sel ? g_wpl : g_wal;
    const int n0 = blockIdx.x * 32, k0 = blockIdx.y * 32;
    const int tx = threadIdx.x, ty = threadIdx.y;
#pragma unroll
    for (int j = 0; j < 32; j += 8)
        tile[ty + j][tx] = W[(size_t)(k0 + ty + j) * N + n0 + tx];
    __syncthreads();
#pragma unroll
    for (int j = 0; j < 32; j += 8) {
        float v = tile[tx][ty + j];
        size_t o = (size_t)(n0 + ty + j) * CC + k0 + tx;
        __nv_bfloat16 h = __float2bfloat16(v);
        Th[o] = h;
        Tl[o] = __float2bfloat16(v - __bfloat162float(h));
    }
}

// ---------------------------------------------------------------------------
// Causal flash attention (verified R1 version; y written split bf16 hi/lo)
// ---------------------------------------------------------------------------
#define ATTN_SMEM_FLOATS (2 * 64 * 65 + 2 * 64 * 68 + 64 * 16 + 3 * 64)

__global__ __launch_bounds__(256) void attn_kernel()
{
    extern __shared__ float smf[];
    float* Qt  = smf;
    float* Pt  = Qt + 64 * 65;
    float* Kt  = Pt + 64 * 65;
    float* Vs  = Kt + 64 * 68;
    float* red = Vs + 64 * 68;
    float* m_s = red + 64 * 16;
    float* l_s = m_s + 64;
    float* fac = l_s + 64;

    const int tid = threadIdx.x;
    const int ty  = tid >> 4, tx = tid & 15;
    const int r0  = ty * 4, c0 = tx * 4;
    const int qt  = blockIdx.x;
    const int bh  = blockIdx.y;
    const int q0  = qt * 64;

    const float* Qg = g_q + (size_t)(bh * TT + q0) * HD;
    const float* Kg = g_k + (size_t)bh * TT * HD;
    const float* Vg = g_v + (size_t)bh * TT * HD;

#pragma unroll
    for (int i = 0; i < 16; i++) {
        int idx = tid + i * 256;
        int row = idx >> 6, d = idx & 63;
        Qt[d * 65 + row] = Qg[row * 64 + d] * 0.125f;
    }
    if (tid < 64) { m_s[tid] = -CUDART_INF_F; l_s[tid] = 0.f; }
    __syncthreads();

    float o[4][4] = {};

    for (int kt = 0; kt <= qt; kt++) {
        const int k0 = kt * 64;
#pragma unroll
        for (int i = 0; i < 16; i++) {
            int idx = tid + i * 256;
            int row = idx >> 6, d = idx & 63;
            Kt[d * 68 + row] = Kg[(size_t)(k0 + row) * 64 + d];
            Vs[row * 68 + d] = Vg[(size_t)(k0 + row) * 64 + d];
        }
        __syncthreads();

        float s[4][4] = {};
#pragma unroll 16
        for (int d = 0; d < 64; d++) {
            float qv[4];
#pragma unroll
            for (int rr = 0; rr < 4; rr++) qv[rr] = Qt[d * 65 + r0 + rr];
            float4 kv = *(float4*)&Kt[d * 68 + c0];
#pragma unroll
            for (int rr = 0; rr < 4; rr++) {
                s[rr][0] += qv[rr] * kv.x;
                s[rr][1] += qv[rr] * kv.y;
                s[rr][2] += qv[rr] * kv.z;
                s[rr][3] += qv[rr] * kv.w;
            }
        }

        if (kt == qt) {
#pragma unroll
            for (int rr = 0; rr < 4; rr++)
#pragma unroll
                for (int cc = 0; cc < 4; cc++)
                    if (c0 + cc > r0 + rr) s[rr][cc] = -CUDART_INF_F;
        }

#pragma unroll
        for (int rr = 0; rr < 4; rr++) {
            float rm = fmaxf(fmaxf(s[rr][0], s[rr][1]), fmaxf(s[rr][2], s[rr][3]));
            red[(r0 + rr) * 16 + tx] = rm;
        }
        __syncthreads();
        if (tid < 64) {
            float mt = red[tid * 16];
#pragma unroll
            for (int j = 1; j < 16; j++) mt = fmaxf(mt, red[tid * 16 + j]);
            float mo = m_s[tid];
            float mn = fmaxf(mo, mt);
            fac[tid] = __expf(mo - mn);
            m_s[tid] = mn;
        }
        __syncthreads();

#pragma unroll
        for (int rr = 0; rr < 4; rr++) {
            float mn = m_s[r0 + rr];
            float rs = 0.f;
#pragma unroll
            for (int cc = 0; cc < 4; cc++) {
                float p = __expf(s[rr][cc] - mn);
                Pt[(c0 + cc) * 65 + r0 + rr] = p;
                rs += p;
            }
            red[(r0 + rr) * 16 + tx] = rs;
        }
        __syncthreads();
        if (tid < 64) {
            float ls = 0.f;
#pragma unroll
            for (int j = 0; j < 16; j++) ls += red[tid * 16 + j];
            l_s[tid] = l_s[tid] * fac[tid] + ls;
        }

#pragma unroll
        for (int rr = 0; rr < 4; rr++) {
            float f = fac[r0 + rr];
#pragma unroll
            for (int cc = 0; cc < 4; cc++) o[rr][cc] *= f;
        }
#pragma unroll 16
        for (int kk = 0; kk < 64; kk++) {
            float pv[4];
#pragma unroll
            for (int rr = 0; rr < 4; rr++) pv[rr] = Pt[kk * 65 + r0 + rr];
            float4 vv = *(float4*)&Vs[kk * 68 + c0];
#pragma unroll
            for (int rr = 0; rr < 4; rr++) {
                o[rr][0] += pv[rr] * vv.x;
                o[rr][1] += pv[rr] * vv.y;
                o[rr][2] += pv[rr] * vv.z;
                o[rr][3] += pv[rr] * vv.w;
            }
        }
        __syncthreads();
    }

    const int b = bh / HH, h = bh % HH;
#pragma unroll
    for (int rr = 0; rr < 4; rr++) {
        float inv = 1.f / l_s[r0 + rr];
        size_t base = (size_t)((b * TT) + q0 + r0 + rr) * CC + h * HD + c0;
#pragma unroll
        for (int cc = 0; cc < 4; cc++) {
            float val = o[rr][cc] * inv;
            __nv_bfloat16 hv = __float2bfloat16(val);
            g_yhi[base + cc] = hv;
            g_ylo[base + cc] = __float2bfloat16(val - __bfloat162float(hv));
        }
    }
}

// ---------------------------------------------------------------------------
extern "C" void kernel_launch(void* const* d_in, const int* in_sizes, int n_in,
                              void* d_out, int out_size)
{
    const float* x      = (const float*)d_in[0];
    const float* W_attn = (const float*)d_in[1];
    const float* b_attn = (const float*)d_in[2];
    const float* W_proj = (const float*)d_in[3];
    const float* b_proj = (const float*)d_in[4];
    float* out = (float*)d_out;

    cudaFuncSetAttribute(attn_kernel, cudaFuncAttributeMaxDynamicSharedMemorySize,
                         ATTN_SMEM_FLOATS * 4);
    cudaFuncSetAttribute(qkv_mm, cudaFuncAttributeMaxDynamicSharedMemorySize, GEMM_SMEM);
    cudaFuncSetAttribute(proj_mm, cudaFuncAttributeMaxDynamicSharedMemorySize, GEMM_SMEM);

    split_x_kernel<<<(MM * CC / 4 + 255) / 256, 256>>>(x);
    {
        dim3 blk(32, 8);
        transpose_split_kernel<<<dim3(N3 / 32, CC / 32), blk>>>(W_attn, 0);
        transpose_split_kernel<<<dim3(CC / 32, CC / 32), blk>>>(W_proj, 1);
    }
    qkv_mm<<<dim3(N3 / 128, MM / 128), 256, GEMM_SMEM>>>(b_attn);
    attn_kernel<<<dim3(TT / 64, BB * HH), 256, ATTN_SMEM_FLOATS * 4>>>();
    proj_mm<<<dim3(CC / 128, MM / 128), 256, GEMM_SMEM>>>(b_proj, out);
}

// round 9
// speedup vs baseline: 2.7056x; 1.5140x over previous
#include <cuda_runtime.h>
#include <cuda_bf16.h>
#include <math_constants.h>
#include <cstdint>

#define BB   8
#define TT   1024
#define CC   768
#define HH   12
#define HD   64
#define MM   (BB * TT)       // 8192
#define N3   (3 * CC)        // 2304

// ---------------------------------------------------------------------------
// Static device scratch (addresses formed ONLY in device code)
// ---------------------------------------------------------------------------
__device__ __align__(16) __nv_bfloat16 g_qh[BB * HH * TT * HD];  // [bh][t][d] (pre-scaled 1/8)
__device__ __align__(16) __nv_bfloat16 g_ql[BB * HH * TT * HD];
__device__ __align__(16) __nv_bfloat16 g_kh[BB * HH * TT * HD];  // [bh][t][d]
__device__ __align__(16) __nv_bfloat16 g_kl[BB * HH * TT * HD];
__device__ __align__(16) __nv_bfloat16 g_vth[BB * HH * HD * TT]; // [bh][d][t] (transposed)
__device__ __align__(16) __nv_bfloat16 g_vtl[BB * HH * HD * TT];

__device__ __align__(16) __nv_bfloat16 g_xhi[MM * CC];
__device__ __align__(16) __nv_bfloat16 g_xlo[MM * CC];
__device__ __align__(16) __nv_bfloat16 g_wah[N3 * CC];   // W_attn^T [N3][CC] hi
__device__ __align__(16) __nv_bfloat16 g_wal[N3 * CC];
__device__ __align__(16) __nv_bfloat16 g_wph[CC * CC];   // W_proj^T hi
__device__ __align__(16) __nv_bfloat16 g_wpl[CC * CC];
__device__ __align__(16) __nv_bfloat16 g_yhi[MM * CC];
__device__ __align__(16) __nv_bfloat16 g_ylo[MM * CC];

// ---------------------------------------------------------------------------
// PTX helpers
// ---------------------------------------------------------------------------
__device__ __forceinline__ uint32_t smem_u32(const void* p) {
    uint32_t a;
    asm("{ .reg .u64 t; cvta.to.shared.u64 t, %1; cvt.u32.u64 %0, t; }" : "=r"(a) : "l"(p));
    return a;
}
__device__ __forceinline__ void mma_bf16(float* d, const uint32_t* a, const uint32_t* b,
                                         const float* c) {
    asm volatile("mma.sync.aligned.m16n8k16.row.col.f32.bf16.bf16.f32 "
                 "{%0,%1,%2,%3}, {%4,%5,%6,%7}, {%8,%9}, {%10,%11,%12,%13};"
                 : "=f"(d[0]), "=f"(d[1]), "=f"(d[2]), "=f"(d[3])
                 : "r"(a[0]), "r"(a[1]), "r"(a[2]), "r"(a[3]), "r"(b[0]), "r"(b[1]),
                   "f"(c[0]), "f"(c[1]), "f"(c[2]), "f"(c[3]));
}
__device__ __forceinline__ void cp16(uint32_t dst, const void* src) {
    asm volatile("cp.async.cg.shared.global [%0], [%1], 16;" :: "r"(dst), "l"(src));
}
__device__ __forceinline__ void cp_commit() {
    asm volatile("cp.async.commit_group;" ::: "memory");
}
template <int N>
__device__ __forceinline__ void cp_wait() {
    asm volatile("cp.async.wait_group %0;" :: "n"(N) : "memory");
}

// Fast exp: magic-number round-to-nearest + degree-5 poly for 2^f, f in [-0.5,0.5].
// Abs poly err ~2.4e-6. Valid for x <= 0 (clamped at -87).
__device__ __forceinline__ float fast_exp(float x) {
    x = fmaxf(x, -87.0f);
    float t = x * 1.4426950408889634f;
    float k = t + 12582912.0f;                 // 1.5 * 2^23
    int   e = __float_as_int(k) - 0x4B400000;  // round(t)
    float f = t - (k - 12582912.0f);           // f in [-0.5, 0.5]
    float p = 1.3333558146e-3f;
    p = fmaf(p, f, 9.6181291076e-3f);
    p = fmaf(p, f, 5.5504108665e-2f);
    p = fmaf(p, f, 2.4022650696e-1f);
    p = fmaf(p, f, 6.9314718056e-1f);
    p = fmaf(p, f, 1.0f);
    return __int_as_float(__float_as_int(p) + (e << 23));
}
__device__ __forceinline__ uint32_t pk_bf16(float a, float b) {
    __nv_bfloat162 h(__float2bfloat16(a), __float2bfloat16(b));
    return *(uint32_t*)&h;
}

// ---------------------------------------------------------------------------
// HMMA GEMM core (verified R6): split-bf16 3-pass, 2-stage cp.async pipeline
// ---------------------------------------------------------------------------
#define ROWB      80
#define TILE_B    (128 * ROWB)
#define STAGE_B   (4 * TILE_B)
#define GEMM_SMEM (2 * STAGE_B)
#define NITER     (CC / 32)

__device__ __forceinline__ void load_stage(const __nv_bfloat16* Ah, const __nv_bfloat16* Al,
                                           const __nv_bfloat16* Bh, const __nv_bfloat16* Bl,
                                           int m0, int n0, int k0,
                                           uint32_t sbase, int tid) {
    const __nv_bfloat16* srcs[4] = {Ah + (size_t)m0 * CC, Al + (size_t)m0 * CC,
                                    Bh + (size_t)n0 * CC, Bl + (size_t)n0 * CC};
#pragma unroll
    for (int i = 0; i < 8; i++) {
        int e = tid + i * 256;
        int t = e >> 9;
        int idx = e & 511;
        int row = idx >> 2, c = idx & 3;
        cp16(sbase + t * TILE_B + row * ROWB + c * 16,
             srcs[t] + (size_t)row * CC + k0 + c * 8);
    }
}

__device__ __forceinline__ void gemm_compute(const char* stage, int lane, int wm, int wn,
                                             float acc[4][4][4]) {
    const char* sAh = stage;
    const char* sAl = stage + TILE_B;
    const char* sBh = stage + 2 * TILE_B;
    const char* sBl = stage + 3 * TILE_B;
    const int g = lane >> 2, q = lane & 3;

#pragma unroll
    for (int kk = 0; kk < 2; kk++) {
        const int kb = kk * 32 + q * 4;
        uint32_t bh[4][2], bl[4][2];
#pragma unroll
        for (int nj = 0; nj < 4; nj++) {
            const int nb = (wn + nj * 8 + g) * ROWB + kb;
            bh[nj][0] = *(const uint32_t*)(sBh + nb);
            bh[nj][1] = *(const uint32_t*)(sBh + nb + 16);
            bl[nj][0] = *(const uint32_t*)(sBl + nb);
            bl[nj][1] = *(const uint32_t*)(sBl + nb + 16);
        }
#pragma unroll
        for (int mi = 0; mi < 4; mi++) {
            const int ab = (wm + mi * 16 + g) * ROWB + kb;
            uint32_t ah[4], al[4];
            ah[0] = *(const uint32_t*)(sAh + ab);
            ah[1] = *(const uint32_t*)(sAh + ab + 8 * ROWB);
            ah[2] = *(const uint32_t*)(sAh + ab + 16);
            ah[3] = *(const uint32_t*)(sAh + ab + 8 * ROWB + 16);
            al[0] = *(const uint32_t*)(sAl + ab);
            al[1] = *(const uint32_t*)(sAl + ab + 8 * ROWB);
            al[2] = *(const uint32_t*)(sAl + ab + 16);
            al[3] = *(const uint32_t*)(sAl + ab + 8 * ROWB + 16);
#pragma unroll
            for (int nj = 0; nj < 4; nj++) {
                mma_bf16(acc[mi][nj], ah, bh[nj], acc[mi][nj]);
                mma_bf16(acc[mi][nj], ah, bl[nj], acc[mi][nj]);
                mma_bf16(acc[mi][nj], al, bh[nj], acc[mi][nj]);
            }
        }
    }
}

__device__ __forceinline__ void gemm_mainloop(const __nv_bfloat16* Ah, const __nv_bfloat16* Al,
                                              const __nv_bfloat16* Bh, const __nv_bfloat16* Bl,
                                              int m0, int n0, char* sm,
                                              int tid, int lane, int wm, int wn,
                                              float acc[4][4][4]) {
    const uint32_t sbase = smem_u32(sm);
    load_stage(Ah, Al, Bh, Bl, m0, n0, 0, sbase, tid);
    cp_commit();
    for (int c = 0; c < NITER; c++) {
        if (c + 1 < NITER) {
            load_stage(Ah, Al, Bh, Bl, m0, n0, (c + 1) * 32,
                       sbase + ((c + 1) & 1) * STAGE_B, tid);
            cp_commit();
            cp_wait<1>();
        } else {
            cp_wait<0>();
        }
        __syncthreads();
        gemm_compute(sm + (c & 1) * STAGE_B, lane, wm, wn, acc);
        __syncthreads();
    }
}

// ---------------------------------------------------------------------------
// QKV GEMM -> split-bf16 Q/K (row-major) and V (transposed), fused bias+scale
// ---------------------------------------------------------------------------
__global__ __launch_bounds__(256, 2) void qkv_mm(const float* __restrict__ bias)
{
    extern __shared__ char sm[];
    const int tid = threadIdx.x, lane = tid & 31, wid = tid >> 5;
    const int wm = (wid & 1) * 64, wn = (wid >> 1) * 32;
    const int m0 = blockIdx.y * 128, n0 = blockIdx.x * 128;

    float acc[4][4][4];
#pragma unroll
    for (int a = 0; a < 4; a++)
#pragma unroll
        for (int b = 0; b < 4; b++)
#pragma unroll
            for (int c = 0; c < 4; c++) acc[a][b][c] = 0.f;

    gemm_mainloop(g_xhi, g_xlo, g_wah, g_wal, m0, n0, sm, tid, lane, wm, wn, acc);

    const int g = lane >> 2, t4 = lane & 3;
    const int which = blockIdx.x / 6;
#pragma unroll
    for (int mi = 0; mi < 4; mi++) {
#pragma unroll
        for (int half = 0; half < 2; half++) {
            const int m = m0 + wm + mi * 16 + g + half * 8;
            const int b_ = m >> 10, t = m & 1023;
#pragma unroll
            for (int nj = 0; nj < 4; nj++) {
                const int n = n0 + wn + nj * 8 + t4 * 2;
                float vx = acc[mi][nj][half * 2 + 0] + __ldg(bias + n);
                float vy = acc[mi][nj][half * 2 + 1] + __ldg(bias + n + 1);
                if (which == 0) { vx *= 0.125f; vy *= 0.125f; }
                const int ccol = n - which * CC;
                const int h = ccol >> 6, d = ccol & 63;
                const int bh = b_ * HH + h;
                __nv_bfloat16 hx = __float2bfloat16(vx);
                __nv_bfloat16 hy = __float2bfloat16(vy);
                __nv_bfloat16 lx = __float2bfloat16(vx - __bfloat162float(hx));
                __nv_bfloat16 ly = __float2bfloat16(vy - __bfloat162float(hy));
                if (which == 2) {
                    size_t o0 = ((size_t)bh * HD + d) * TT + t;
                    g_vth[o0] = hx; g_vth[o0 + TT] = hy;
                    g_vtl[o0] = lx; g_vtl[o0 + TT] = ly;
                } else {
                    size_t o0 = ((size_t)bh * TT + t) * HD + d;
                    __nv_bfloat162 h2(hx, hy), l2(lx, ly);
                    if (which == 0) {
                        *(__nv_bfloat162*)(g_qh + o0) = h2;
                        *(__nv_bfloat162*)(g_ql + o0) = l2;
                    } else {
                        *(__nv_bfloat162*)(g_kh + o0) = h2;
                        *(__nv_bfloat162*)(g_kl + o0) = l2;
                    }
                }
            }
        }
    }
}

// ---------------------------------------------------------------------------
// Proj GEMM -> out fp32 [M][CC] with bias
// ---------------------------------------------------------------------------
__global__ __launch_bounds__(256, 2) void proj_mm(const float* __restrict__ bias,
                                                  float* __restrict__ out)
{
    extern __shared__ char sm[];
    const int tid = threadIdx.x, lane = tid & 31, wid = tid >> 5;
    const int wm = (wid & 1) * 64, wn = (wid >> 1) * 32;
    const int m0 = blockIdx.y * 128, n0 = blockIdx.x * 128;

    float acc[4][4][4];
#pragma unroll
    for (int a = 0; a < 4; a++)
#pragma unroll
        for (int b = 0; b < 4; b++)
#pragma unroll
            for (int c = 0; c < 4; c++) acc[a][b][c] = 0.f;

    gemm_mainloop(g_yhi, g_ylo, g_wph, g_wpl, m0, n0, sm, tid, lane, wm, wn, acc);

    const int g = lane >> 2, t4 = lane & 3;
#pragma unroll
    for (int mi = 0; mi < 4; mi++) {
#pragma unroll
        for (int half = 0; half < 2; half++) {
            const int m = m0 + wm + mi * 16 + g + half * 8;
#pragma unroll
            for (int nj = 0; nj < 4; nj++) {
                const int n = n0 + wn + nj * 8 + t4 * 2;
                float2 v;
                v.x = acc[mi][nj][half * 2 + 0] + __ldg(bias + n);
                v.y = acc[mi][nj][half * 2 + 1] + __ldg(bias + n + 1);
                *(float2*)(out + (size_t)m * CC + n) = v;
            }
        }
    }
}

// ---------------------------------------------------------------------------
// Conversion kernels (globals referenced from device code only)
// ---------------------------------------------------------------------------
__global__ void split_x_kernel(const float* __restrict__ src)
{
    int i = blockIdx.x * blockDim.x + threadIdx.x;
    if (i >= MM * CC / 4) return;
    float4 v = ((const float4*)src)[i];
    __nv_bfloat16 h0 = __float2bfloat16(v.x);
    __nv_bfloat16 h1 = __float2bfloat16(v.y);
    __nv_bfloat16 h2 = __float2bfloat16(v.z);
    __nv_bfloat16 h3 = __float2bfloat16(v.w);
    __nv_bfloat162* hp = (__nv_bfloat162*)g_xhi;
    __nv_bfloat162* lp = (__nv_bfloat162*)g_xlo;
    hp[i * 2 + 0] = __nv_bfloat162(h0, h1);
    hp[i * 2 + 1] = __nv_bfloat162(h2, h3);
    lp[i * 2 + 0] = __nv_bfloat162(__float2bfloat16(v.x - __bfloat162float(h0)),
                                   __float2bfloat16(v.y - __bfloat162float(h1)));
    lp[i * 2 + 1] = __nv_bfloat162(__float2bfloat16(v.z - __bfloat162float(h2)),
                                   __float2bfloat16(v.w - __bfloat162float(h3)));
}

__global__ void transpose_split_kernel(const float* __restrict__ W, int sel)
{
    __shared__ float tile[32][33];
    const int N = sel ? CC : N3;
    __nv_bfloat16* Th = sel ? g_wph : g_wah;
    __nv_bfloat16* Tl = sel ? g_wpl : g_wal;
    const int n0 = blockIdx.x * 32, k0 = blockIdx.y * 32;
    const int tx = threadIdx.x, ty = threadIdx.y;
#pragma unroll
    for (int j = 0; j < 32; j += 8)
        tile[ty + j][tx] = W[(size_t)(k0 + ty + j) * N + n0 + tx];
    __syncthreads();
#pragma unroll
    for (int j = 0; j < 32; j += 8) {
        float v = tile[tx][ty + j];
        size_t o = (size_t)(n0 + ty + j) * CC + k0 + tx;
        __nv_bfloat16 h = __float2bfloat16(v);
        Th[o] = h;
        Tl[o] = __float2bfloat16(v - __bfloat162float(h));
    }
}

// ---------------------------------------------------------------------------
// HMMA flash attention: 128 Q rows/block, 8 warps, K/V tiles of 64,
// split-bf16 3-pass S and PV, online softmax with fast_exp.
// ---------------------------------------------------------------------------
#define AP       144
#define QB       (2 * 128 * AP)   // Qh + Ql        = 36864
#define KVTILE   (64 * AP)        //                = 9216
#define STG      (4 * KVTILE)     // Kh,Kl,Vh,Vl    = 36864
#define ATTN_SMEM (QB + 2 * STG)  //                = 110592

__device__ __forceinline__ void load_kv_stage(int bh, int kt, uint32_t dstb, int tid) {
    const __nv_bfloat16* kb[2] = {g_kh + ((size_t)bh * TT + kt * 64) * HD,
                                  g_kl + ((size_t)bh * TT + kt * 64) * HD};
    const __nv_bfloat16* vb[2] = {g_vth + (size_t)bh * HD * TT + kt * 64,
                                  g_vtl + (size_t)bh * HD * TT + kt * 64};
#pragma unroll
    for (int i = 0; i < 8; i++) {
        int e = tid + i * 256;            // 0..2047
        int t = e >> 9;                   // tile 0..3 (Kh,Kl,Vh,Vl)
        int idx = e & 511;
        int row = idx >> 3, c = idx & 7;
        const __nv_bfloat16* src = (t < 2) ? (kb[t] + (size_t)row * HD + c * 8)
                                           : (vb[t - 2] + (size_t)row * TT + c * 8);
        cp16(dstb + t * KVTILE + row * AP + c * 16, src);
    }
}

__global__ __launch_bounds__(256, 2) void attn_mma()
{
    extern __shared__ char sm[];
    char* sQh = sm;
    char* sQl = sm + 128 * AP;
    const int tid = threadIdx.x, lane = tid & 31, wid = tid >> 5;
    const int g = lane >> 2, q4 = lane & 3;
    const int qt = blockIdx.x, bh = blockIdx.y;
    const int q0 = qt * 128, wm = wid * 16;
    const uint32_t sb = smem_u32(sm);
    const int nkt = 2 * qt + 2;

    // Q tiles (hi/lo) -> smem
    {
        const __nv_bfloat16* qsrc[2] = {g_qh + ((size_t)bh * TT + q0) * HD,
                                        g_ql + ((size_t)bh * TT + q0) * HD};
#pragma unroll
        for (int i = 0; i < 8; i++) {
            int e = tid + i * 256;         // 0..2047
            int bf = e >> 10;              // 0=hi, 1=lo
            int idx = e & 1023;
            int row = idx >> 3, c = idx & 7;
            cp16(sb + bf * 128 * AP + row * AP + c * 16,
                 qsrc[bf] + (size_t)row * HD + c * 8);
        }
    }
    load_kv_stage(bh, 0, sb + QB, tid);
    cp_commit();

    float o[8][4];
#pragma unroll
    for (int a = 0; a < 8; a++)
#pragma unroll
        for (int b = 0; b < 4; b++) o[a][b] = 0.f;
    float mr0 = -1e30f, mr1 = -1e30f, l0 = 0.f, l1 = 0.f;

    for (int kt = 0; kt < nkt; kt++) {
        if (kt + 1 < nkt) {
            load_kv_stage(bh, kt + 1, sb + QB + ((kt + 1) & 1) * STG, tid);
            cp_commit();
            cp_wait<1>();
        } else {
            cp_wait<0>();
        }
        __syncthreads();

        const char* st  = sm + QB + (kt & 1) * STG;
        const char* sKh = st;
        const char* sKl = st + KVTILE;
        const char* sVh = st + 2 * KVTILE;
        const char* sVl = st + 3 * KVTILE;

        // ---- S = Q K^T (3-pass) ----
        float s[8][4];
#pragma unroll
        for (int a = 0; a < 8; a++)
#pragma unroll
            for (int b = 0; b < 4; b++) s[a][b] = 0.f;

#pragma unroll
        for (int kc = 0; kc < 4; kc++) {
            const int qa = (wm + g) * AP + kc * 32 + q4 * 4;
            uint32_t qh[4], ql[4];
            qh[0] = *(const uint32_t*)(sQh + qa);
            qh[1] = *(const uint32_t*)(sQh + qa + 8 * AP);
            qh[2] = *(const uint32_t*)(sQh + qa + 16);
            qh[3] = *(const uint32_t*)(sQh + qa + 8 * AP + 16);
            ql[0] = *(const uint32_t*)(sQl + qa);
            ql[1] = *(const uint32_t*)(sQl + qa + 8 * AP);
            ql[2] = *(const uint32_t*)(sQl + qa + 16);
            ql[3] = *(const uint32_t*)(sQl + qa + 8 * AP + 16);
#pragma unroll
            for (int nt = 0; nt < 8; nt++) {
                const int ka = (nt * 8 + g) * AP + kc * 32 + q4 * 4;
                uint32_t kh2[2], kl2[2];
                kh2[0] = *(const uint32_t*)(sKh + ka);
                kh2[1] = *(const uint32_t*)(sKh + ka + 16);
                kl2[0] = *(const uint32_t*)(sKl + ka);
                kl2[1] = *(const uint32_t*)(sKl + ka + 16);
                mma_bf16(s[nt], qh, kh2, s[nt]);
                mma_bf16(s[nt], qh, kl2, s[nt]);
                mma_bf16(s[nt], ql, kh2, s[nt]);
            }
        }

        // ---- causal mask (only the two diagonal tiles) ----
        if (kt >= 2 * qt) {
            const int r0g = q0 + wm + g;
#pragma unroll
            for (int nt = 0; nt < 8; nt++) {
                const int cb = kt * 64 + nt * 8 + 2 * q4;
                if (cb > r0g)          s[nt][0] = -1e30f;
                if (cb + 1 > r0g)      s[nt][1] = -1e30f;
                if (cb > r0g + 8)      s[nt][2] = -1e30f;
                if (cb + 1 > r0g + 8)  s[nt][3] = -1e30f;
            }
        }

        // ---- online softmax ----
        float mx0 = s[0][0], mx1 = s[0][2];
#pragma unroll
        for (int nt = 0; nt < 8; nt++) {
            mx0 = fmaxf(mx0, fmaxf(s[nt][0], s[nt][1]));
            mx1 = fmaxf(mx1, fmaxf(s[nt][2], s[nt][3]));
        }
        mx0 = fmaxf(mx0, __shfl_xor_sync(0xffffffff, mx0, 1));
        mx0 = fmaxf(mx0, __shfl_xor_sync(0xffffffff, mx0, 2));
        mx1 = fmaxf(mx1, __shfl_xor_sync(0xffffffff, mx1, 1));
        mx1 = fmaxf(mx1, __shfl_xor_sync(0xffffffff, mx1, 2));
        const float mn0 = fmaxf(mr0, mx0), mn1 = fmaxf(mr1, mx1);
        const float f0 = fast_exp(mr0 - mn0), f1 = fast_exp(mr1 - mn1);
        mr0 = mn0; mr1 = mn1;
        l0 *= f0; l1 *= f1;
#pragma unroll
        for (int dt = 0; dt < 8; dt++) {
            o[dt][0] *= f0; o[dt][1] *= f0;
            o[dt][2] *= f1; o[dt][3] *= f1;
        }
        float ps0 = 0.f, ps1 = 0.f;
#pragma unroll
        for (int nt = 0; nt < 8; nt++) {
            s[nt][0] = fast_exp(s[nt][0] - mn0);
            s[nt][1] = fast_exp(s[nt][1] - mn0);
            s[nt][2] = fast_exp(s[nt][2] - mn1);
            s[nt][3] = fast_exp(s[nt][3] - mn1);
            ps0 += s[nt][0] + s[nt][1];
            ps1 += s[nt][2] + s[nt][3];
        }
        l0 += ps0; l1 += ps1;

        // ---- O += P V (3-pass; P fragments built in registers) ----
#pragma unroll
        for (int kc2 = 0; kc2 < 4; kc2++) {
            const int nt0 = 2 * kc2, nt1 = nt0 + 1;
            uint32_t aph[4], apl[4];
            {
                float p00 = s[nt0][0], p01 = s[nt0][1], p02 = s[nt0][2], p03 = s[nt0][3];
                float p10 = s[nt1][0], p11 = s[nt1][1], p12 = s[nt1][2], p13 = s[nt1][3];
                aph[0] = pk_bf16(p00, p01);
                aph[1] = pk_bf16(p02, p03);
                aph[2] = pk_bf16(p10, p11);
                aph[3] = pk_bf16(p12, p13);
                __nv_bfloat162* h;
                h = (__nv_bfloat162*)&aph[0];
                apl[0] = pk_bf16(p00 - __bfloat162float(h->x), p01 - __bfloat162float(h->y));
                h = (__nv_bfloat162*)&aph[1];
                apl[1] = pk_bf16(p02 - __bfloat162float(h->x), p03 - __bfloat162float(h->y));
                h = (__nv_bfloat162*)&aph[2];
                apl[2] = pk_bf16(p10 - __bfloat162float(h->x), p11 - __bfloat162float(h->y));
                h = (__nv_bfloat162*)&aph[3];
                apl[3] = pk_bf16(p12 - __bfloat162float(h->x), p13 - __bfloat162float(h->y));
            }
#pragma unroll
            for (int dt = 0; dt < 8; dt++) {
                const int va = (dt * 8 + g) * AP + kc2 * 32 + q4 * 4;
                uint32_t vh2[2], vl2[2];
                vh2[0] = *(const uint32_t*)(sVh + va);
                vh2[1] = *(const uint32_t*)(sVh + va + 16);
                vl2[0] = *(const uint32_t*)(sVl + va);
                vl2[1] = *(const uint32_t*)(sVl + va + 16);
                mma_bf16(o[dt], aph, vh2, o[dt]);
                mma_bf16(o[dt], aph, vl2, o[dt]);
                mma_bf16(o[dt], apl, vh2, o[dt]);
            }
        }
        __syncthreads();
    }

    // ---- finalize: normalize and write y (split bf16 hi/lo) ----
    l0 += __shfl_xor_sync(0xffffffff, l0, 1);
    l0 += __shfl_xor_sync(0xffffffff, l0, 2);
    l1 += __shfl_xor_sync(0xffffffff, l1, 1);
    l1 += __shfl_xor_sync(0xffffffff, l1, 2);
    const float inv0 = 1.f / l0, inv1 = 1.f / l1;

    const int b = bh / HH, h = bh % HH;
    const int t0 = q0 + wm + g, t1 = t0 + 8;
#pragma unroll
    for (int dt = 0; dt < 8; dt++) {
        const int d = dt * 8 + 2 * q4;
        {
            float vx = o[dt][0] * inv0, vy = o[dt][1] * inv0;
            size_t off = (size_t)(b * TT + t0) * CC + h * HD + d;
            __nv_bfloat16 hx = __float2bfloat16(vx), hy = __float2bfloat16(vy);
            *(__nv_bfloat162*)(g_yhi + off) = __nv_bfloat162(hx, hy);
            *(__nv_bfloat162*)(g_ylo + off) =
                __nv_bfloat162(__float2bfloat16(vx - __bfloat162float(hx)),
                               __float2bfloat16(vy - __bfloat162float(hy)));
        }
        {
            float vx = o[dt][2] * inv1, vy = o[dt][3] * inv1;
            size_t off = (size_t)(b * TT + t1) * CC + h * HD + d;
            __nv_bfloat16 hx = __float2bfloat16(vx), hy = __float2bfloat16(vy);
            *(__nv_bfloat162*)(g_yhi + off) = __nv_bfloat162(hx, hy);
            *(__nv_bfloat162*)(g_ylo + off) =
                __nv_bfloat162(__float2bfloat16(vx - __bfloat162float(hx)),
                               __float2bfloat16(vy - __bfloat162float(hy)));
        }
    }
}

// ---------------------------------------------------------------------------
extern "C" void kernel_launch(void* const* d_in, const int* in_sizes, int n_in,
                              void* d_out, int out_size)
{
    const float* x      = (const float*)d_in[0];
    const float* W_attn = (const float*)d_in[1];
    const float* b_attn = (const float*)d_in[2];
    const float* W_proj = (const float*)d_in[3];
    const float* b_proj = (const float*)d_in[4];
    float* out = (float*)d_out;

    cudaFuncSetAttribute(qkv_mm, cudaFuncAttributeMaxDynamicSharedMemorySize, GEMM_SMEM);
    cudaFuncSetAttribute(proj_mm, cudaFuncAttributeMaxDynamicSharedMemorySize, GEMM_SMEM);
    cudaFuncSetAttribute(attn_mma, cudaFuncAttributeMaxDynamicSharedMemorySize, ATTN_SMEM);

    split_x_kernel<<<(MM * CC / 4 + 255) / 256, 256>>>(x);
    {
        dim3 blk(32, 8);
        transpose_split_kernel<<<dim3(N3 / 32, CC / 32), blk>>>(W_attn, 0);
        transpose_split_kernel<<<dim3(CC / 32, CC / 32), blk>>>(W_proj, 1);
    }
    qkv_mm<<<dim3(N3 / 128, MM / 128), 256, GEMM_SMEM>>>(b_attn);
    attn_mma<<<dim3(TT / 128, BB * HH), 256, ATTN_SMEM>>>();
    proj_mm<<<dim3(CC / 128, MM / 128), 256, GEMM_SMEM>>>(b_proj, out);
}

// round 13
// speedup vs baseline: 2.8883x; 1.0675x over previous
#include <cuda_runtime.h>
#include <cuda_bf16.h>
#include <math_constants.h>
#include <cstdint>

#define BB   8
#define TT   1024
#define CC   768
#define HH   12
#define HD   64
#define MM   (BB * TT)       // 8192
#define N3   (3 * CC)        // 2304

// ---------------------------------------------------------------------------
// Static device scratch (addresses formed ONLY in device code)
// ---------------------------------------------------------------------------
__device__ __align__(16) __nv_bfloat16 g_qh[BB * HH * TT * HD];  // [bh][t][d] (pre-scaled 1/8)
__device__ __align__(16) __nv_bfloat16 g_ql[BB * HH * TT * HD];
__device__ __align__(16) __nv_bfloat16 g_kh[BB * HH * TT * HD];  // [bh][t][d]
__device__ __align__(16) __nv_bfloat16 g_kl[BB * HH * TT * HD];
__device__ __align__(16) __nv_bfloat16 g_vth[BB * HH * HD * TT]; // [bh][d][t] (transposed)
__device__ __align__(16) __nv_bfloat16 g_vtl[BB * HH * HD * TT];

__device__ __align__(16) __nv_bfloat16 g_xhi[MM * CC];
__device__ __align__(16) __nv_bfloat16 g_xlo[MM * CC];
__device__ __align__(16) __nv_bfloat16 g_wah[N3 * CC];   // W_attn^T [N3][CC] hi
__device__ __align__(16) __nv_bfloat16 g_wal[N3 * CC];
__device__ __align__(16) __nv_bfloat16 g_wph[CC * CC];   // W_proj^T hi
__device__ __align__(16) __nv_bfloat16 g_wpl[CC * CC];
__device__ __align__(16) __nv_bfloat16 g_yhi[MM * CC];
__device__ __align__(16) __nv_bfloat16 g_ylo[MM * CC];

// ---------------------------------------------------------------------------
// PTX helpers
// ---------------------------------------------------------------------------
__device__ __forceinline__ uint32_t smem_u32(const void* p) {
    uint32_t a;
    asm("{ .reg .u64 t; cvta.to.shared.u64 t, %1; cvt.u32.u64 %0, t; }" : "=r"(a) : "l"(p));
    return a;
}
__device__ __forceinline__ void ldm_x4(uint32_t* r, uint32_t addr) {
    asm volatile("ldmatrix.sync.aligned.m8n8.x4.shared.b16 {%0,%1,%2,%3}, [%4];"
                 : "=r"(r[0]), "=r"(r[1]), "=r"(r[2]), "=r"(r[3]) : "r"(addr));
}
__device__ __forceinline__ void mma_bf16(float* d, const uint32_t* a, const uint32_t* b,
                                         const float* c) {
    asm volatile("mma.sync.aligned.m16n8k16.row.col.f32.bf16.bf16.f32 "
                 "{%0,%1,%2,%3}, {%4,%5,%6,%7}, {%8,%9}, {%10,%11,%12,%13};"
                 : "=f"(d[0]), "=f"(d[1]), "=f"(d[2]), "=f"(d[3])
                 : "r"(a[0]), "r"(a[1]), "r"(a[2]), "r"(a[3]), "r"(b[0]), "r"(b[1]),
                   "f"(c[0]), "f"(c[1]), "f"(c[2]), "f"(c[3]));
}
__device__ __forceinline__ void cp16(uint32_t dst, const void* src) {
    asm volatile("cp.async.cg.shared.global [%0], [%1], 16;" :: "r"(dst), "l"(src));
}
__device__ __forceinline__ void cp_commit() {
    asm volatile("cp.async.commit_group;" ::: "memory");
}
template <int N>
__device__ __forceinline__ void cp_wait() {
    asm volatile("cp.async.wait_group %0;" :: "n"(N) : "memory");
}

// Fast exp: magic-number round + degree-5 poly for 2^f. Abs err ~2.4e-6.
__device__ __forceinline__ float fast_exp(float x) {
    x = fmaxf(x, -87.0f);
    float t = x * 1.4426950408889634f;
    float k = t + 12582912.0f;                 // 1.5 * 2^23
    int   e = __float_as_int(k) - 0x4B400000;
    float f = t - (k - 12582912.0f);
    float p = 1.3333558146e-3f;
    p = fmaf(p, f, 9.6181291076e-3f);
    p = fmaf(p, f, 5.5504108665e-2f);
    p = fmaf(p, f, 2.4022650696e-1f);
    p = fmaf(p, f, 6.9314718056e-1f);
    p = fmaf(p, f, 1.0f);
    return __int_as_float(__float_as_int(p) + (e << 23));
}
__device__ __forceinline__ uint32_t pk_bf16(float a, float b) {
    __nv_bfloat162 h(__float2bfloat16(a), __float2bfloat16(b));
    return *(uint32_t*)&h;
}

// ---------------------------------------------------------------------------
// HMMA GEMM core: split-bf16 3-pass, 2-stage cp.async, ldmatrix fragments
// ---------------------------------------------------------------------------
#define ROWB      80
#define TILE_B    (128 * ROWB)
#define STAGE_B   (4 * TILE_B)
#define GEMM_SMEM (2 * STAGE_B)
#define NITER     (CC / 32)

__device__ __forceinline__ void load_stage(const __nv_bfloat16* Ah, const __nv_bfloat16* Al,
                                           const __nv_bfloat16* Bh, const __nv_bfloat16* Bl,
                                           int m0, int n0, int k0,
                                           uint32_t sbase, int tid) {
    const __nv_bfloat16* srcs[4] = {Ah + (size_t)m0 * CC, Al + (size_t)m0 * CC,
                                    Bh + (size_t)n0 * CC, Bl + (size_t)n0 * CC};
#pragma unroll
    for (int i = 0; i < 8; i++) {
        int e = tid + i * 256;
        int t = e >> 9;
        int idx = e & 511;
        int row = idx >> 2, c = idx & 3;
        cp16(sbase + t * TILE_B + row * ROWB + c * 16,
             srcs[t] + (size_t)row * CC + k0 + c * 8);
    }
}

__device__ __forceinline__ void gemm_compute(uint32_t stage, int lane, int wm, int wn,
                                             float acc[4][4][4]) {
    const uint32_t sAh = stage;
    const uint32_t sAl = stage + TILE_B;
    const uint32_t sBh = stage + 2 * TILE_B;
    const uint32_t sBl = stage + 3 * TILE_B;
    const int arow = lane & 15;
    const int achunk = lane >> 4;                     // 0/1 -> +16B (k8-15)
    const int brow = (lane & 7) + ((lane >> 4) << 3); // phases: n0-7,n0-7,n8-15,n8-15
    const int bchunk = (lane >> 3) & 1;

#pragma unroll
    for (int kk = 0; kk < 2; kk++) {
        const uint32_t aoff = kk * 32 + achunk * 16;
        const uint32_t boff = kk * 32 + bchunk * 16;
        uint32_t ah[4][4], al[4][4], bh[2][4], bl[2][4];
#pragma unroll
        for (int bj = 0; bj < 2; bj++) {
            ldm_x4(bh[bj], sBh + (wn + bj * 16 + brow) * ROWB + boff);
            ldm_x4(bl[bj], sBl + (wn + bj * 16 + brow) * ROWB + boff);
        }
#pragma unroll
        for (int mi = 0; mi < 4; mi++) {
            ldm_x4(ah[mi], sAh + (wm + mi * 16 + arow) * ROWB + aoff);
            ldm_x4(al[mi], sAl + (wm + mi * 16 + arow) * ROWB + aoff);
        }
#pragma unroll
        for (int mi = 0; mi < 4; mi++)
#pragma unroll
            for (int nj = 0; nj < 4; nj++) {
                mma_bf16(acc[mi][nj], ah[mi], &bh[nj >> 1][(nj & 1) * 2], acc[mi][nj]);
                mma_bf16(acc[mi][nj], ah[mi], &bl[nj >> 1][(nj & 1) * 2], acc[mi][nj]);
                mma_bf16(acc[mi][nj], al[mi], &bh[nj >> 1][(nj & 1) * 2], acc[mi][nj]);
            }
    }
}

__device__ __forceinline__ void gemm_mainloop(const __nv_bfloat16* Ah, const __nv_bfloat16* Al,
                                              const __nv_bfloat16* Bh, const __nv_bfloat16* Bl,
                                              int m0, int n0, char* sm,
                                              int tid, int lane, int wm, int wn,
                                              float acc[4][4][4]) {
    const uint32_t sbase = smem_u32(sm);
    load_stage(Ah, Al, Bh, Bl, m0, n0, 0, sbase, tid);
    cp_commit();
    for (int c = 0; c < NITER; c++) {
        if (c + 1 < NITER) {
            load_stage(Ah, Al, Bh, Bl, m0, n0, (c + 1) * 32,
                       sbase + ((c + 1) & 1) * STAGE_B, tid);
            cp_commit();
            cp_wait<1>();
        } else {
            cp_wait<0>();
        }
        __syncthreads();
        gemm_compute(sbase + (c & 1) * STAGE_B, lane, wm, wn, acc);
        __syncthreads();
    }
}

// ---------------------------------------------------------------------------
// QKV GEMM -> split-bf16 Q/K (row-major) and V (transposed), fused bias+scale
// ---------------------------------------------------------------------------
__global__ __launch_bounds__(256, 2) void qkv_mm(const float* __restrict__ bias)
{
    extern __shared__ char sm[];
    const int tid = threadIdx.x, lane = tid & 31, wid = tid >> 5;
    const int wm = (wid & 1) * 64, wn = (wid >> 1) * 32;
    const int m0 = blockIdx.y * 128, n0 = blockIdx.x * 128;

    float acc[4][4][4];
#pragma unroll
    for (int a = 0; a < 4; a++)
#pragma unroll
        for (int b = 0; b < 4; b++)
#pragma unroll
            for (int c = 0; c < 4; c++) acc[a][b][c] = 0.f;

    gemm_mainloop(g_xhi, g_xlo, g_wah, g_wal, m0, n0, sm, tid, lane, wm, wn, acc);

    const int g = lane >> 2, t4 = lane & 3;
    const int which = blockIdx.x / 6;
#pragma unroll
    for (int mi = 0; mi < 4; mi++) {
#pragma unroll
        for (int half = 0; half < 2; half++) {
            const int m = m0 + wm + mi * 16 + g + half * 8;
            const int b_ = m >> 10, t = m & 1023;
#pragma unroll
            for (int nj = 0; nj < 4; nj++) {
                const int n = n0 + wn + nj * 8 + t4 * 2;
                float vx = acc[mi][nj][half * 2 + 0] + __ldg(bias + n);
                float vy = acc[mi][nj][half * 2 + 1] + __ldg(bias + n + 1);
                if (which == 0) { vx *= 0.125f; vy *= 0.125f; }
                const int ccol = n - which * CC;
                const int h = ccol >> 6, d = ccol & 63;
                const int bh = b_ * HH + h;
                __nv_bfloat16 hx = __float2bfloat16(vx);
                __nv_bfloat16 hy = __float2bfloat16(vy);
                __nv_bfloat16 lx = __float2bfloat16(vx - __bfloat162float(hx));
                __nv_bfloat16 ly = __float2bfloat16(vy - __bfloat162float(hy));
                if (which == 2) {
                    size_t o0 = ((size_t)bh * HD + d) * TT + t;
                    g_vth[o0] = hx; g_vth[o0 + TT] = hy;
                    g_vtl[o0] = lx; g_vtl[o0 + TT] = ly;
                } else {
                    size_t o0 = ((size_t)bh * TT + t) * HD + d;
                    __nv_bfloat162 h2(hx, hy), l2(lx, ly);
                    if (which == 0) {
                        *(__nv_bfloat162*)(g_qh + o0) = h2;
                        *(__nv_bfloat162*)(g_ql + o0) = l2;
                    } else {
                        *(__nv_bfloat162*)(g_kh + o0) = h2;
                        *(__nv_bfloat162*)(g_kl + o0) = l2;
                    }
                }
            }
        }
    }
}

// ---------------------------------------------------------------------------
// Proj GEMM -> out fp32 [M][CC] with bias
// ---------------------------------------------------------------------------
__global__ __launch_bounds__(256, 2) void proj_mm(const float* __restrict__ bias,
                                                  float* __restrict__ out)
{
    extern __shared__ char sm[];
    const int tid = threadIdx.x, lane = tid & 31, wid = tid >> 5;
    const int wm = (wid & 1) * 64, wn = (wid >> 1) * 32;
    const int m0 = blockIdx.y * 128, n0 = blockIdx.x * 128;

    float acc[4][4][4];
#pragma unroll
    for (int a = 0; a < 4; a++)
#pragma unroll
        for (int b = 0; b < 4; b++)
#pragma unroll
            for (int c = 0; c < 4; c++) acc[a][b][c] = 0.f;

    gemm_mainloop(g_yhi, g_ylo, g_wph, g_wpl, m0, n0, sm, tid, lane, wm, wn, acc);

    const int g = lane >> 2, t4 = lane & 3;
#pragma unroll
    for (int mi = 0; mi < 4; mi++) {
#pragma unroll
        for (int half = 0; half < 2; half++) {
            const int m = m0 + wm + mi * 16 + g + half * 8;
#pragma unroll
            for (int nj = 0; nj < 4; nj++) {
                const int n = n0 + wn + nj * 8 + t4 * 2;
                float2 v;
                v.x = acc[mi][nj][half * 2 + 0] + __ldg(bias + n);
                v.y = acc[mi][nj][half * 2 + 1] + __ldg(bias + n + 1);
                *(float2*)(out + (size_t)m * CC + n) = v;
            }
        }
    }
}

// ---------------------------------------------------------------------------
// Conversion kernels (globals referenced from device code only)
// ---------------------------------------------------------------------------
__global__ void split_x_kernel(const float* __restrict__ src)
{
    int i = blockIdx.x * blockDim.x + threadIdx.x;
    if (i >= MM * CC / 4) return;
    float4 v = ((const float4*)src)[i];
    __nv_bfloat16 h0 = __float2bfloat16(v.x);
    __nv_bfloat16 h1 = __float2bfloat16(v.y);
    __nv_bfloat16 h2 = __float2bfloat16(v.z);
    __nv_bfloat16 h3 = __float2bfloat16(v.w);
    __nv_bfloat162* hp = (__nv_bfloat162*)g_xhi;
    __nv_bfloat162* lp = (__nv_bfloat162*)g_xlo;
    hp[i * 2 + 0] = __nv_bfloat162(h0, h1);
    hp[i * 2 + 1] = __nv_bfloat162(h2, h3);
    lp[i * 2 + 0] = __nv_bfloat162(__float2bfloat16(v.x - __bfloat162float(h0)),
                                   __float2bfloat16(v.y - __bfloat162float(h1)));
    lp[i * 2 + 1] = __nv_bfloat162(__float2bfloat16(v.z - __bfloat162float(h2)),
                                   __float2bfloat16(v.w - __bfloat162float(h3)));
}

__global__ void transpose_split_kernel(const float* __restrict__ W, int sel)
{
    __shared__ float tile[32][33];
    const int N = sel ? CC : N3;
    __nv_bfloat16* Th = sel ? g_wph : g_wah;
    __nv_bfloat16* Tl = sel ? g_wpl : g_wal;
    const int n0 = blockIdx.x * 32, k0 = blockIdx.y * 32;
    const int tx = threadIdx.x, ty = threadIdx.y;
#pragma unroll
    for (int j = 0; j < 32; j += 8)
        tile[ty + j][tx] = W[(size_t)(k0 + ty + j) * N + n0 + tx];
    __syncthreads();
#pragma unroll
    for (int j = 0; j < 32; j += 8) {
        float v = tile[tx][ty + j];
        size_t o = (size_t)(n0 + ty + j) * CC + k0 + tx;
        __nv_bfloat16 h = __float2bfloat16(v);
        Th[o] = h;
        Tl[o] = __float2bfloat16(v - __bfloat162float(h));
    }
}

// ---------------------------------------------------------------------------
// HMMA flash attention (ldmatrix fragments)
// ---------------------------------------------------------------------------
#define AP       144
#define QB       (2 * 128 * AP)
#define KVTILE   (64 * AP)
#define STG      (4 * KVTILE)
#define ATTN_SMEM (QB + 2 * STG)

__device__ __forceinline__ void load_kv_stage(int bh, int kt, uint32_t dstb, int tid) {
    const __nv_bfloat16* kb[2] = {g_kh + ((size_t)bh * TT + kt * 64) * HD,
                                  g_kl + ((size_t)bh * TT + kt * 64) * HD};
    const __nv_bfloat16* vb[2] = {g_vth + (size_t)bh * HD * TT + kt * 64,
                                  g_vtl + (size_t)bh * HD * TT + kt * 64};
#pragma unroll
    for (int i = 0; i < 8; i++) {
        int e = tid + i * 256;
        int t = e >> 9;
        int idx = e & 511;
        int row = idx >> 3, c = idx & 7;
        const __nv_bfloat16* src = (t < 2) ? (kb[t] + (size_t)row * HD + c * 8)
                                           : (vb[t - 2] + (size_t)row * TT + c * 8);
        cp16(dstb + t * KVTILE + row * AP + c * 16, src);
    }
}

__global__ __launch_bounds__(256, 2) void attn_mma()
{
    extern __shared__ char sm[];
    const int tid = threadIdx.x, lane = tid & 31, wid = tid >> 5;
    const int g = lane >> 2, q4 = lane & 3;
    const int qt = blockIdx.x, bh = blockIdx.y;
    const int q0 = qt * 128, wm = wid * 16;
    const uint32_t sb = smem_u32(sm);
    const uint32_t sQh = sb, sQl = sb + 128 * AP;
    const int nkt = 2 * qt + 2;

    const int arow = lane & 15;
    const int achunk = lane >> 4;
    const int brow = (lane & 7) + ((lane >> 4) << 3);
    const int bchunk = (lane >> 3) & 1;

    // Q tiles (hi/lo) -> smem
    {
        const __nv_bfloat16* qsrc[2] = {g_qh + ((size_t)bh * TT + q0) * HD,
                                        g_ql + ((size_t)bh * TT + q0) * HD};
#pragma unroll
        for (int i = 0; i < 8; i++) {
            int e = tid + i * 256;
            int bf = e >> 10;
            int idx = e & 1023;
            int row = idx >> 3, c = idx & 7;
            cp16(sb + bf * 128 * AP + row * AP + c * 16,
                 qsrc[bf] + (size_t)row * HD + c * 8);
        }
    }
    load_kv_stage(bh, 0, sb + QB, tid);
    cp_commit();

    float o[8][4];
#pragma unroll
    for (int a = 0; a < 8; a++)
#pragma unroll
        for (int b = 0; b < 4; b++) o[a][b] = 0.f;
    float mr0 = -1e30f, mr1 = -1e30f, l0 = 0.f, l1 = 0.f;

    for (int kt = 0; kt < nkt; kt++) {
        if (kt + 1 < nkt) {
            load_kv_stage(bh, kt + 1, sb + QB + ((kt + 1) & 1) * STG, tid);
            cp_commit();
            cp_wait<1>();
        } else {
            cp_wait<0>();
        }
        __syncthreads();

        const uint32_t st  = sb + QB + (kt & 1) * STG;
        const uint32_t sKh = st;
        const uint32_t sKl = st + KVTILE;
        const uint32_t sVh = st + 2 * KVTILE;
        const uint32_t sVl = st + 3 * KVTILE;

        // ---- S = Q K^T (3-pass, ldmatrix) ----
        float s[8][4];
#pragma unroll
        for (int a = 0; a < 8; a++)
#pragma unroll
            for (int b = 0; b < 4; b++) s[a][b] = 0.f;

#pragma unroll
        for (int kc = 0; kc < 4; kc++) {
            uint32_t qh[4], ql[4];
            ldm_x4(qh, sQh + (wm + arow) * AP + kc * 32 + achunk * 16);
            ldm_x4(ql, sQl + (wm + arow) * AP + kc * 32 + achunk * 16);
#pragma unroll
            for (int p = 0; p < 4; p++) {   // nt pairs: nt = 2p, 2p+1
                uint32_t kh2[4], kl2[4];
                ldm_x4(kh2, sKh + (p * 16 + brow) * AP + kc * 32 + bchunk * 16);
                ldm_x4(kl2, sKl + (p * 16 + brow) * AP + kc * 32 + bchunk * 16);
                mma_bf16(s[2 * p],     qh, &kh2[0], s[2 * p]);
                mma_bf16(s[2 * p],     qh, &kl2[0], s[2 * p]);
                mma_bf16(s[2 * p],     ql, &kh2[0], s[2 * p]);
                mma_bf16(s[2 * p + 1], qh, &kh2[2], s[2 * p + 1]);
                mma_bf16(s[2 * p + 1], qh, &kl2[2], s[2 * p + 1]);
                mma_bf16(s[2 * p + 1], ql, &kh2[2], s[2 * p + 1]);
            }
        }

        // ---- causal mask (diagonal tiles only) ----
        if (kt >= 2 * qt) {
            const int r0g = q0 + wm + g;
#pragma unroll
            for (int nt = 0; nt < 8; nt++) {
                const int cb = kt * 64 + nt * 8 + 2 * q4;
                if (cb > r0g)          s[nt][0] = -1e30f;
                if (cb + 1 > r0g)      s[nt][1] = -1e30f;
                if (cb > r0g + 8)      s[nt][2] = -1e30f;
                if (cb + 1 > r0g + 8)  s[nt][3] = -1e30f;
            }
        }

        // ---- online softmax ----
        float mx0 = s[0][0], mx1 = s[0][2];
#pragma unroll
        for (int nt = 0; nt < 8; nt++) {
            mx0 = fmaxf(mx0, fmaxf(s[nt][0], s[nt][1]));
            mx1 = fmaxf(mx1, fmaxf(s[nt][2], s[nt][3]));
        }
        mx0 = fmaxf(mx0, __shfl_xor_sync(0xffffffff, mx0, 1));
        mx0 = fmaxf(mx0, __shfl_xor_sync(0xffffffff, mx0, 2));
        mx1 = fmaxf(mx1, __shfl_xor_sync(0xffffffff, mx1, 1));
        mx1 = fmaxf(mx1, __shfl_xor_sync(0xffffffff, mx1, 2));
        const float mn0 = fmaxf(mr0, mx0), mn1 = fmaxf(mr1, mx1);
        const float f0 = fast_exp(mr0 - mn0), f1 = fast_exp(mr1 - mn1);
        mr0 = mn0; mr1 = mn1;
        l0 *= f0; l1 *= f1;
#pragma unroll
        for (int dt = 0; dt < 8; dt++) {
            o[dt][0] *= f0; o[dt][1] *= f0;
            o[dt][2] *= f1; o[dt][3] *= f1;
        }
        float ps0 = 0.f, ps1 = 0.f;
#pragma unroll
        for (int nt = 0; nt < 8; nt++) {
            s[nt][0] = fast_exp(s[nt][0] - mn0);
            s[nt][1] = fast_exp(s[nt][1] - mn0);
            s[nt][2] = fast_exp(s[nt][2] - mn1);
            s[nt][3] = fast_exp(s[nt][3] - mn1);
            ps0 += s[nt][0] + s[nt][1];
            ps1 += s[nt][2] + s[nt][3];
        }
        l0 += ps0; l1 += ps1;

        // ---- O += P V (3-pass; P fragments in registers, V via ldmatrix) ----
#pragma unroll
        for (int kc2 = 0; kc2 < 4; kc2++) {
            const int nt0 = 2 * kc2, nt1 = nt0 + 1;
            uint32_t aph[4], apl[4];
            {
                float p00 = s[nt0][0], p01 = s[nt0][1], p02 = s[nt0][2], p03 = s[nt0][3];
                float p10 = s[nt1][0], p11 = s[nt1][1], p12 = s[nt1][2], p13 = s[nt1][3];
                aph[0] = pk_bf16(p00, p01);
                aph[1] = pk_bf16(p02, p03);
                aph[2] = pk_bf16(p10, p11);
                aph[3] = pk_bf16(p12, p13);
                __nv_bfloat162* h;
                h = (__nv_bfloat162*)&aph[0];
                apl[0] = pk_bf16(p00 - __bfloat162float(h->x), p01 - __bfloat162float(h->y));
                h = (__nv_bfloat162*)&aph[1];
                apl[1] = pk_bf16(p02 - __bfloat162float(h->x), p03 - __bfloat162float(h->y));
                h = (__nv_bfloat162*)&aph[2];
                apl[2] = pk_bf16(p10 - __bfloat162float(h->x), p11 - __bfloat162float(h->y));
                h = (__nv_bfloat162*)&aph[3];
                apl[3] = pk_bf16(p12 - __bfloat162float(h->x), p13 - __bfloat162float(h->y));
            }
#pragma unroll
            for (int p = 0; p < 4; p++) {   // dt pairs: dt = 2p, 2p+1
                uint32_t vh2[4], vl2[4];
                ldm_x4(vh2, sVh + (p * 16 + brow) * AP + kc2 * 32 + bchunk * 16);
                ldm_x4(vl2, sVl + (p * 16 + brow) * AP + kc2 * 32 + bchunk * 16);
                mma_bf16(o[2 * p],     aph, &vh2[0], o[2 * p]);
                mma_bf16(o[2 * p],     aph, &vl2[0], o[2 * p]);
                mma_bf16(o[2 * p],     apl, &vh2[0], o[2 * p]);
                mma_bf16(o[2 * p + 1], aph, &vh2[2], o[2 * p + 1]);
                mma_bf16(o[2 * p + 1], aph, &vl2[2], o[2 * p + 1]);
                mma_bf16(o[2 * p + 1], apl, &vh2[2], o[2 * p + 1]);
            }
        }
        __syncthreads();
    }

    // ---- finalize: normalize and write y (split bf16 hi/lo) ----
    l0 += __shfl_xor_sync(0xffffffff, l0, 1);
    l0 += __shfl_xor_sync(0xffffffff, l0, 2);
    l1 += __shfl_xor_sync(0xffffffff, l1, 1);
    l1 += __shfl_xor_sync(0xffffffff, l1, 2);
    const float inv0 = 1.f / l0, inv1 = 1.f / l1;

    const int b = bh / HH, h = bh % HH;
    const int t0 = q0 + wm + g, t1 = t0 + 8;
#pragma unroll
    for (int dt = 0; dt < 8; dt++) {
        const int d = dt * 8 + 2 * q4;
        {
            float vx = o[dt][0] * inv0, vy = o[dt][1] * inv0;
            size_t off = (size_t)(b * TT + t0) * CC + h * HD + d;
            __nv_bfloat16 hx = __float2bfloat16(vx), hy = __float2bfloat16(vy);
            *(__nv_bfloat162*)(g_yhi + off) = __nv_bfloat162(hx, hy);
            *(__nv_bfloat162*)(g_ylo + off) =
                __nv_bfloat162(__float2bfloat16(vx - __bfloat162float(hx)),
                               __float2bfloat16(vy - __bfloat162float(hy)));
        }
        {
            float vx = o[dt][2] * inv1, vy = o[dt][3] * inv1;
            size_t off = (size_t)(b * TT + t1) * CC + h * HD + d;
            __nv_bfloat16 hx = __float2bfloat16(vx), hy = __float2bfloat16(vy);
            *(__nv_bfloat162*)(g_yhi + off) = __nv_bfloat162(hx, hy);
            *(__nv_bfloat162*)(g_ylo + off) =
                __nv_bfloat162(__float2bfloat16(vx - __bfloat162float(hx)),
                               __float2bfloat16(vy - __bfloat162float(hy)));
        }
    }
}

// ---------------------------------------------------------------------------
extern "C" void kernel_launch(void* const* d_in, const int* in_sizes, int n_in,
                              void* d_out, int out_size)
{
    const float* x      = (const float*)d_in[0];
    const float* W_attn = (const float*)d_in[1];
    const float* b_attn = (const float*)d_in[2];
    const float* W_proj = (const float*)d_in[3];
    const float* b_proj = (const float*)d_in[4];
    float* out = (float*)d_out;

    cudaFuncSetAttribute(qkv_mm, cudaFuncAttributeMaxDynamicSharedMemorySize, GEMM_SMEM);
    cudaFuncSetAttribute(proj_mm, cudaFuncAttributeMaxDynamicSharedMemorySize, GEMM_SMEM);
    cudaFuncSetAttribute(attn_mma, cudaFuncAttributeMaxDynamicSharedMemorySize, ATTN_SMEM);

    split_x_kernel<<<(MM * CC / 4 + 255) / 256, 256>>>(x);
    {
        dim3 blk(32, 8);
        transpose_split_kernel<<<dim3(N3 / 32, CC / 32), blk>>>(W_attn, 0);
        transpose_split_kernel<<<dim3(CC / 32, CC / 32), blk>>>(W_proj, 1);
    }
    qkv_mm<<<dim3(N3 / 128, MM / 128), 256, GEMM_SMEM>>>(b_attn);
    attn_mma<<<dim3(TT / 128, BB * HH), 256, ATTN_SMEM>>>();
    proj_mm<<<dim3(CC / 128, MM / 128), 256, GEMM_SMEM>>>(b_proj, out);
}

// round 14
// speedup vs baseline: 3.9470x; 1.3666x over previous
#include <cuda_runtime.h>
#include <cuda_fp16.h>
#include <math_constants.h>
#include <cstdint>

#define BB   8
#define TT   1024
#define CC   768
#define HH   12
#define HD   64
#define MM   (BB * TT)       // 8192
#define N3   (3 * CC)        // 2304

// ---------------------------------------------------------------------------
// Static device scratch (addresses formed ONLY in device code)
// ---------------------------------------------------------------------------
__device__ __align__(16) __half g_qh[BB * HH * TT * HD];  // [bh][t][d] split hi (pre-scaled 1/8)
__device__ __align__(16) __half g_ql[BB * HH * TT * HD];  // split lo
__device__ __align__(16) __half g_k [BB * HH * TT * HD];  // [bh][t][d] single fp16
__device__ __align__(16) __half g_vt[BB * HH * HD * TT];  // [bh][d][t] single fp16 (transposed)

__device__ __align__(16) __half g_xh[MM * CC];            // X split hi
__device__ __align__(16) __half g_xl[MM * CC];            // X split lo
__device__ __align__(16) __half g_wa[N3 * CC];            // W_attn^T [N3][CC] single fp16
__device__ __align__(16) __half g_wp[CC * CC];            // W_proj^T single fp16
__device__ __align__(16) __half g_yh[MM * CC];            // y split hi
__device__ __align__(16) __half g_yl[MM * CC];            // y split lo

// ---------------------------------------------------------------------------
// PTX helpers
// ---------------------------------------------------------------------------
__device__ __forceinline__ uint32_t smem_u32(const void* p) {
    uint32_t a;
    asm("{ .reg .u64 t; cvta.to.shared.u64 t, %1; cvt.u32.u64 %0, t; }" : "=r"(a) : "l"(p));
    return a;
}
__device__ __forceinline__ void ldm_x4(uint32_t* r, uint32_t addr) {
    asm volatile("ldmatrix.sync.aligned.m8n8.x4.shared.b16 {%0,%1,%2,%3}, [%4];"
                 : "=r"(r[0]), "=r"(r[1]), "=r"(r[2]), "=r"(r[3]) : "r"(addr));
}
__device__ __forceinline__ void mma_f16(float* d, const uint32_t* a, const uint32_t* b,
                                        const float* c) {
    asm volatile("mma.sync.aligned.m16n8k16.row.col.f32.f16.f16.f32 "
                 "{%0,%1,%2,%3}, {%4,%5,%6,%7}, {%8,%9}, {%10,%11,%12,%13};"
                 : "=f"(d[0]), "=f"(d[1]), "=f"(d[2]), "=f"(d[3])
                 : "r"(a[0]), "r"(a[1]), "r"(a[2]), "r"(a[3]), "r"(b[0]), "r"(b[1]),
                   "f"(c[0]), "f"(c[1]), "f"(c[2]), "f"(c[3]));
}
__device__ __forceinline__ void cp16(uint32_t dst, const void* src) {
    asm volatile("cp.async.cg.shared.global [%0], [%1], 16;" :: "r"(dst), "l"(src));
}
__device__ __forceinline__ void cp_commit() {
    asm volatile("cp.async.commit_group;" ::: "memory");
}
template <int N>
__device__ __forceinline__ void cp_wait() {
    asm volatile("cp.async.wait_group %0;" :: "n"(N) : "memory");
}

// Fast exp: magic-number round + degree-5 poly for 2^f. Abs err ~2.4e-6.
__device__ __forceinline__ float fast_exp(float x) {
    x = fmaxf(x, -87.0f);
    float t = x * 1.4426950408889634f;
    float k = t + 12582912.0f;                 // 1.5 * 2^23
    int   e = __float_as_int(k) - 0x4B400000;
    float f = t - (k - 12582912.0f);
    float p = 1.3333558146e-3f;
    p = fmaf(p, f, 9.6181291076e-3f);
    p = fmaf(p, f, 5.5504108665e-2f);
    p = fmaf(p, f, 2.4022650696e-1f);
    p = fmaf(p, f, 6.9314718056e-1f);
    p = fmaf(p, f, 1.0f);
    return __int_as_float(__float_as_int(p) + (e << 23));
}
__device__ __forceinline__ uint32_t packh(__half a, __half b) {
    __half2 h(a, b);
    return *(uint32_t*)&h;
}

// ---------------------------------------------------------------------------
// fp16 GEMM core: 2-pass (A split hi/lo, B single), 2-stage cp.async,
// ldmatrix fragments. Tiles: 128 rows x 32 fp16, pitch 80 B.
// ---------------------------------------------------------------------------
#define ROWB      80
#define TILE_B    (128 * ROWB)          // 10240
#define STAGE_B   (3 * TILE_B)          // Ah, Al, B = 30720
#define GEMM_SMEM (2 * STAGE_B)         // 61440
#define NITER     (CC / 32)             // 24

__device__ __forceinline__ void load_stage(const __half* Ah, const __half* Al,
                                           const __half* B,
                                           int m0, int n0, int k0,
                                           uint32_t sbase, int tid) {
    const __half* srcs[3] = {Ah + (size_t)m0 * CC, Al + (size_t)m0 * CC,
                             B + (size_t)n0 * CC};
#pragma unroll
    for (int i = 0; i < 6; i++) {
        int e = tid + i * 256;            // 0..1535
        int t = e >> 9;                   // tile 0..2
        int idx = e & 511;
        int row = idx >> 2, c = idx & 3;  // 4 x 16B per row
        cp16(sbase + t * TILE_B + row * ROWB + c * 16,
             srcs[t] + (size_t)row * CC + k0 + c * 8);
    }
}

__device__ __forceinline__ void gemm_compute(uint32_t stage, int lane, int wm, int wn,
                                             float acc[4][4][4]) {
    const uint32_t sAh = stage;
    const uint32_t sAl = stage + TILE_B;
    const uint32_t sB  = stage + 2 * TILE_B;
    const int arow = lane & 15;
    const int achunk = lane >> 4;                     // 0/1 -> +16B (k8-15)
    const int brow = (lane & 7) + ((lane >> 4) << 3); // phases: n0-7,n0-7,n8-15,n8-15
    const int bchunk = (lane >> 3) & 1;

#pragma unroll
    for (int kk = 0; kk < 2; kk++) {
        const uint32_t aoff = kk * 32 + achunk * 16;
        const uint32_t boff = kk * 32 + bchunk * 16;
        uint32_t ah[4][4], al[4][4], bb[2][4];
#pragma unroll
        for (int bj = 0; bj < 2; bj++)
            ldm_x4(bb[bj], sB + (wn + bj * 16 + brow) * ROWB + boff);
#pragma unroll
        for (int mi = 0; mi < 4; mi++) {
            ldm_x4(ah[mi], sAh + (wm + mi * 16 + arow) * ROWB + aoff);
            ldm_x4(al[mi], sAl + (wm + mi * 16 + arow) * ROWB + aoff);
        }
#pragma unroll
        for (int mi = 0; mi < 4; mi++)
#pragma unroll
            for (int nj = 0; nj < 4; nj++) {
                mma_f16(acc[mi][nj], ah[mi], &bb[nj >> 1][(nj & 1) * 2], acc[mi][nj]);
                mma_f16(acc[mi][nj], al[mi], &bb[nj >> 1][(nj & 1) * 2], acc[mi][nj]);
            }
    }
}

__device__ __forceinline__ void gemm_mainloop(const __half* Ah, const __half* Al,
                                              const __half* B,
                                              int m0, int n0, char* sm,
                                              int tid, int lane, int wm, int wn,
                                              float acc[4][4][4]) {
    const uint32_t sbase = smem_u32(sm);
    load_stage(Ah, Al, B, m0, n0, 0, sbase, tid);
    cp_commit();
    for (int c = 0; c < NITER; c++) {
        if (c + 1 < NITER) {
            load_stage(Ah, Al, B, m0, n0, (c + 1) * 32,
                       sbase + ((c + 1) & 1) * STAGE_B, tid);
            cp_commit();
            cp_wait<1>();
        } else {
            cp_wait<0>();
        }
        __syncthreads();
        gemm_compute(sbase + (c & 1) * STAGE_B, lane, wm, wn, acc);
        __syncthreads();
    }
}

// ---------------------------------------------------------------------------
// QKV GEMM -> q split fp16 (scaled), k single fp16, v single fp16 transposed
// ---------------------------------------------------------------------------
__global__ __launch_bounds__(256, 2) void qkv_mm(const float* __restrict__ bias)
{
    extern __shared__ char sm[];
    const int tid = threadIdx.x, lane = tid & 31, wid = tid >> 5;
    const int wm = (wid & 1) * 64, wn = (wid >> 1) * 32;
    const int m0 = blockIdx.y * 128, n0 = blockIdx.x * 128;

    float acc[4][4][4];
#pragma unroll
    for (int a = 0; a < 4; a++)
#pragma unroll
        for (int b = 0; b < 4; b++)
#pragma unroll
            for (int c = 0; c < 4; c++) acc[a][b][c] = 0.f;

    gemm_mainloop(g_xh, g_xl, g_wa, m0, n0, sm, tid, lane, wm, wn, acc);

    const int g = lane >> 2, t4 = lane & 3;
    const int which = blockIdx.x / 6;
#pragma unroll
    for (int mi = 0; mi < 4; mi++) {
#pragma unroll
        for (int half = 0; half < 2; half++) {
            const int m = m0 + wm + mi * 16 + g + half * 8;
            const int b_ = m >> 10, t = m & 1023;
#pragma unroll
            for (int nj = 0; nj < 4; nj++) {
                const int n = n0 + wn + nj * 8 + t4 * 2;
                float vx = acc[mi][nj][half * 2 + 0] + __ldg(bias + n);
                float vy = acc[mi][nj][half * 2 + 1] + __ldg(bias + n + 1);
                const int ccol = n - which * CC;
                const int h = ccol >> 6, d = ccol & 63;
                const int bh = b_ * HH + h;
                if (which == 0) {
                    vx *= 0.125f; vy *= 0.125f;
                    __half hx = __float2half_rn(vx), hy = __float2half_rn(vy);
                    __half lx = __float2half_rn(vx - __half2float(hx));
                    __half ly = __float2half_rn(vy - __half2float(hy));
                    size_t o0 = ((size_t)bh * TT + t) * HD + d;
                    *(__half2*)(g_qh + o0) = __half2(hx, hy);
                    *(__half2*)(g_ql + o0) = __half2(lx, ly);
                } else if (which == 1) {
                    size_t o0 = ((size_t)bh * TT + t) * HD + d;
                    *(__half2*)(g_k + o0) = __floats2half2_rn(vx, vy);
                } else {
                    size_t o0 = ((size_t)bh * HD + d) * TT + t;
                    g_vt[o0]      = __float2half_rn(vx);
                    g_vt[o0 + TT] = __float2half_rn(vy);
                }
            }
        }
    }
}

// ---------------------------------------------------------------------------
// Proj GEMM -> out fp32 [M][CC] with bias
// ---------------------------------------------------------------------------
__global__ __launch_bounds__(256, 2) void proj_mm(const float* __restrict__ bias,
                                                  float* __restrict__ out)
{
    extern __shared__ char sm[];
    const int tid = threadIdx.x, lane = tid & 31, wid = tid >> 5;
    const int wm = (wid & 1) * 64, wn = (wid >> 1) * 32;
    const int m0 = blockIdx.y * 128, n0 = blockIdx.x * 128;

    float acc[4][4][4];
#pragma unroll
    for (int a = 0; a < 4; a++)
#pragma unroll
        for (int b = 0; b < 4; b++)
#pragma unroll
            for (int c = 0; c < 4; c++) acc[a][b][c] = 0.f;

    gemm_mainloop(g_yh, g_yl, g_wp, m0, n0, sm, tid, lane, wm, wn, acc);

    const int g = lane >> 2, t4 = lane & 3;
#pragma unroll
    for (int mi = 0; mi < 4; mi++) {
#pragma unroll
        for (int half = 0; half < 2; half++) {
            const int m = m0 + wm + mi * 16 + g + half * 8;
#pragma unroll
            for (int nj = 0; nj < 4; nj++) {
                const int n = n0 + wn + nj * 8 + t4 * 2;
                float2 v;
                v.x = acc[mi][nj][half * 2 + 0] + __ldg(bias + n);
                v.y = acc[mi][nj][half * 2 + 1] + __ldg(bias + n + 1);
                *(float2*)(out + (size_t)m * CC + n) = v;
            }
        }
    }
}

// ---------------------------------------------------------------------------
// Conversion kernels (globals referenced from device code only)
// ---------------------------------------------------------------------------
__global__ void split_x_kernel(const float* __restrict__ src)
{
    int i = blockIdx.x * blockDim.x + threadIdx.x;
    if (i >= MM * CC / 4) return;
    float4 v = ((const float4*)src)[i];
    __half h0 = __float2half_rn(v.x);
    __half h1 = __float2half_rn(v.y);
    __half h2 = __float2half_rn(v.z);
    __half h3 = __float2half_rn(v.w);
    __half2* hp = (__half2*)g_xh;
    __half2* lp = (__half2*)g_xl;
    hp[i * 2 + 0] = __half2(h0, h1);
    hp[i * 2 + 1] = __half2(h2, h3);
    lp[i * 2 + 0] = __half2(__float2half_rn(v.x - __half2float(h0)),
                            __float2half_rn(v.y - __half2float(h1)));
    lp[i * 2 + 1] = __half2(__float2half_rn(v.z - __half2float(h2)),
                            __float2half_rn(v.w - __half2float(h3)));
}

// W[K=CC][N] -> T[N][K] single fp16.  sel: 0 = W_attn (N=N3), 1 = W_proj
__global__ void transpose_split_kernel(const float* __restrict__ W, int sel)
{
    __shared__ float tile[32][33];
    const int N = sel ? CC : N3;
    __half* Th = sel ? g_wp : g_wa;
    const int n0 = blockIdx.x * 32, k0 = blockIdx.y * 32;
    const int tx = threadIdx.x, ty = threadIdx.y;
#pragma unroll
    for (int j = 0; j < 32; j += 8)
        tile[ty + j][tx] = W[(size_t)(k0 + ty + j) * N + n0 + tx];
    __syncthreads();
#pragma unroll
    for (int j = 0; j < 32; j += 8)
        Th[(size_t)(n0 + ty + j) * CC + k0 + tx] = __float2half_rn(tile[tx][ty + j]);
}

// ---------------------------------------------------------------------------
// fp16 HMMA flash attention: S 2-pass (Q split, K single), PV 2-pass
// (P split in regs, V single).  K/V stage is 2 tiles (halved traffic).
// ---------------------------------------------------------------------------
#define AP        144
#define QB        (2 * 128 * AP)   // Qh + Ql = 36864
#define KVTILE    (64 * AP)        // 9216
#define STG       (2 * KVTILE)     // K, V = 18432
#define ATTN_SMEM (QB + 2 * STG)   // 73728

__device__ __forceinline__ void load_kv_stage(int bh, int kt, uint32_t dstb, int tid) {
    const __half* kb = g_k + ((size_t)bh * TT + kt * 64) * HD;
    const __half* vb = g_vt + (size_t)bh * HD * TT + kt * 64;
#pragma unroll
    for (int i = 0; i < 4; i++) {
        int e = tid + i * 256;            // 0..1023
        int t = e >> 9;                   // 0=K, 1=V
        int idx = e & 511;
        int row = idx >> 3, c = idx & 7;
        const __half* src = (t == 0) ? (kb + (size_t)row * HD + c * 8)
                                     : (vb + (size_t)row * TT + c * 8);
        cp16(dstb + t * KVTILE + row * AP + c * 16, src);
    }
}

__global__ __launch_bounds__(256, 2) void attn_mma()
{
    extern __shared__ char sm[];
    const int tid = threadIdx.x, lane = tid & 31, wid = tid >> 5;
    const int g = lane >> 2, q4 = lane & 3;
    const int qt = blockIdx.x, bh = blockIdx.y;
    const int q0 = qt * 128, wm = wid * 16;
    const uint32_t sb = smem_u32(sm);
    const uint32_t sQh = sb, sQl = sb + 128 * AP;
    const int nkt = 2 * qt + 2;

    const int arow = lane & 15;
    const int achunk = lane >> 4;
    const int brow = (lane & 7) + ((lane >> 4) << 3);
    const int bchunk = (lane >> 3) & 1;

    // Q tiles (hi/lo) -> smem
    {
        const __half* qsrc[2] = {g_qh + ((size_t)bh * TT + q0) * HD,
                                 g_ql + ((size_t)bh * TT + q0) * HD};
#pragma unroll
        for (int i = 0; i < 8; i++) {
            int e = tid + i * 256;
            int bf = e >> 10;
            int idx = e & 1023;
            int row = idx >> 3, c = idx & 7;
            cp16(sb + bf * 128 * AP + row * AP + c * 16,
                 qsrc[bf] + (size_t)row * HD + c * 8);
        }
    }
    load_kv_stage(bh, 0, sb + QB, tid);
    cp_commit();

    float o[8][4];
#pragma unroll
    for (int a = 0; a < 8; a++)
#pragma unroll
        for (int b = 0; b < 4; b++) o[a][b] = 0.f;
    float mr0 = -1e30f, mr1 = -1e30f, l0 = 0.f, l1 = 0.f;

    for (int kt = 0; kt < nkt; kt++) {
        if (kt + 1 < nkt) {
            load_kv_stage(bh, kt + 1, sb + QB + ((kt + 1) & 1) * STG, tid);
            cp_commit();
            cp_wait<1>();
        } else {
            cp_wait<0>();
        }
        __syncthreads();

        const uint32_t st = sb + QB + (kt & 1) * STG;
        const uint32_t sK = st;
        const uint32_t sV = st + KVTILE;

        // ---- S = Q K^T (2-pass: Qh·K + Ql·K) ----
        float s[8][4];
#pragma unroll
        for (int a = 0; a < 8; a++)
#pragma unroll
            for (int b = 0; b < 4; b++) s[a][b] = 0.f;

#pragma unroll
        for (int kc = 0; kc < 4; kc++) {
            uint32_t qh[4], ql[4];
            ldm_x4(qh, sQh + (wm + arow) * AP + kc * 32 + achunk * 16);
            ldm_x4(ql, sQl + (wm + arow) * AP + kc * 32 + achunk * 16);
#pragma unroll
            for (int p = 0; p < 4; p++) {   // nt pairs: nt = 2p, 2p+1
                uint32_t kk2[4];
                ldm_x4(kk2, sK + (p * 16 + brow) * AP + kc * 32 + bchunk * 16);
                mma_f16(s[2 * p],     qh, &kk2[0], s[2 * p]);
                mma_f16(s[2 * p],     ql, &kk2[0], s[2 * p]);
                mma_f16(s[2 * p + 1], qh, &kk2[2], s[2 * p + 1]);
                mma_f16(s[2 * p + 1], ql, &kk2[2], s[2 * p + 1]);
            }
        }

        // ---- causal mask (diagonal tiles only) ----
        if (kt >= 2 * qt) {
            const int r0g = q0 + wm + g;
#pragma unroll
            for (int nt = 0; nt < 8; nt++) {
                const int cb = kt * 64 + nt * 8 + 2 * q4;
                if (cb > r0g)          s[nt][0] = -1e30f;
                if (cb + 1 > r0g)      s[nt][1] = -1e30f;
                if (cb > r0g + 8)      s[nt][2] = -1e30f;
                if (cb + 1 > r0g + 8)  s[nt][3] = -1e30f;
            }
        }

        // ---- online softmax ----
        float mx0 = s[0][0], mx1 = s[0][2];
#pragma unroll
        for (int nt = 0; nt < 8; nt++) {
            mx0 = fmaxf(mx0, fmaxf(s[nt][0], s[nt][1]));
            mx1 = fmaxf(mx1, fmaxf(s[nt][2], s[nt][3]));
        }
        mx0 = fmaxf(mx0, __shfl_xor_sync(0xffffffff, mx0, 1));
        mx0 = fmaxf(mx0, __shfl_xor_sync(0xffffffff, mx0, 2));
        mx1 = fmaxf(mx1, __shfl_xor_sync(0xffffffff, mx1, 1));
        mx1 = fmaxf(mx1, __shfl_xor_sync(0xffffffff, mx1, 2));
        const float mn0 = fmaxf(mr0, mx0), mn1 = fmaxf(mr1, mx1);
        const float f0 = fast_exp(mr0 - mn0), f1 = fast_exp(mr1 - mn1);
        mr0 = mn0; mr1 = mn1;
        l0 *= f0; l1 *= f1;
#pragma unroll
        for (int dt = 0; dt < 8; dt++) {
            o[dt][0] *= f0; o[dt][1] *= f0;
            o[dt][2] *= f1; o[dt][3] *= f1;
        }
        float ps0 = 0.f, ps1 = 0.f;
#pragma unroll
        for (int nt = 0; nt < 8; nt++) {
            s[nt][0] = fast_exp(s[nt][0] - mn0);
            s[nt][1] = fast_exp(s[nt][1] - mn0);
            s[nt][2] = fast_exp(s[nt][2] - mn1);
            s[nt][3] = fast_exp(s[nt][3] - mn1);
            ps0 += s[nt][0] + s[nt][1];
            ps1 += s[nt][2] + s[nt][3];
        }
        l0 += ps0; l1 += ps1;

        // ---- O += P V (2-pass: Ph·V + Pl·V; P fragments in registers) ----
#pragma unroll
        for (int kc2 = 0; kc2 < 4; kc2++) {
            const int nt0 = 2 * kc2, nt1 = nt0 + 1;
            uint32_t aph[4], apl[4];
            {
                float p00 = s[nt0][0], p01 = s[nt0][1], p02 = s[nt0][2], p03 = s[nt0][3];
                float p10 = s[nt1][0], p11 = s[nt1][1], p12 = s[nt1][2], p13 = s[nt1][3];
                __half h00 = __float2half_rn(p00), h01 = __float2half_rn(p01);
                __half h02 = __float2half_rn(p02), h03 = __float2half_rn(p03);
                __half h10 = __float2half_rn(p10), h11 = __float2half_rn(p11);
                __half h12 = __float2half_rn(p12), h13 = __float2half_rn(p13);
                aph[0] = packh(h00, h01);
                aph[1] = packh(h02, h03);
                aph[2] = packh(h10, h11);
                aph[3] = packh(h12, h13);
                apl[0] = packh(__float2half_rn(p00 - __half2float(h00)),
                               __float2half_rn(p01 - __half2float(h01)));
                apl[1] = packh(__float2half_rn(p02 - __half2float(h02)),
                               __float2half_rn(p03 - __half2float(h03)));
                apl[2] = packh(__float2half_rn(p10 - __half2float(h10)),
                               __float2half_rn(p11 - __half2float(h11)));
                apl[3] = packh(__float2half_rn(p12 - __half2float(h12)),
                               __float2half_rn(p13 - __half2float(h13)));
            }
#pragma unroll
            for (int p = 0; p < 4; p++) {   // dt pairs: dt = 2p, 2p+1
                uint32_t vv2[4];
                ldm_x4(vv2, sV + (p * 16 + brow) * AP + kc2 * 32 + bchunk * 16);
                mma_f16(o[2 * p],     aph, &vv2[0], o[2 * p]);
                mma_f16(o[2 * p],     apl, &vv2[0], o[2 * p]);
                mma_f16(o[2 * p + 1], aph, &vv2[2], o[2 * p + 1]);
                mma_f16(o[2 * p + 1], apl, &vv2[2], o[2 * p + 1]);
            }
        }
        __syncthreads();
    }

    // ---- finalize: normalize and write y (split fp16 hi/lo) ----
    l0 += __shfl_xor_sync(0xffffffff, l0, 1);
    l0 += __shfl_xor_sync(0xffffffff, l0, 2);
    l1 += __shfl_xor_sync(0xffffffff, l1, 1);
    l1 += __shfl_xor_sync(0xffffffff, l1, 2);
    const float inv0 = 1.f / l0, inv1 = 1.f / l1;

    const int b = bh / HH, h = bh % HH;
    const int t0 = q0 + wm + g, t1 = t0 + 8;
#pragma unroll
    for (int dt = 0; dt < 8; dt++) {
        const int d = dt * 8 + 2 * q4;
        {
            float vx = o[dt][0] * inv0, vy = o[dt][1] * inv0;
            size_t off = (size_t)(b * TT + t0) * CC + h * HD + d;
            __half hx = __float2half_rn(vx), hy = __float2half_rn(vy);
            *(__half2*)(g_yh + off) = __half2(hx, hy);
            *(__half2*)(g_yl + off) = __half2(__float2half_rn(vx - __half2float(hx)),
                                              __float2half_rn(vy - __half2float(hy)));
        }
        {
            float vx = o[dt][2] * inv1, vy = o[dt][3] * inv1;
            size_t off = (size_t)(b * TT + t1) * CC + h * HD + d;
            __half hx = __float2half_rn(vx), hy = __float2half_rn(vy);
            *(__half2*)(g_yh + off) = __half2(hx, hy);
            *(__half2*)(g_yl + off) = __half2(__float2half_rn(vx - __half2float(hx)),
                                              __float2half_rn(vy - __half2float(hy)));
        }
    }
}

// ---------------------------------------------------------------------------
extern "C" void kernel_launch(void* const* d_in, const int* in_sizes, int n_in,
                              void* d_out, int out_size)
{
    const float* x      = (const float*)d_in[0];
    const float* W_attn = (const float*)d_in[1];
    const float* b_attn = (const float*)d_in[2];
    const float* W_proj = (const float*)d_in[3];
    const float* b_proj = (const float*)d_in[4];
    float* out = (float*)d_out;

    cudaFuncSetAttribute(qkv_mm, cudaFuncAttributeMaxDynamicSharedMemorySize, GEMM_SMEM);
    cudaFuncSetAttribute(proj_mm, cudaFuncAttributeMaxDynamicSharedMemorySize, GEMM_SMEM);
    cudaFuncSetAttribute(attn_mma, cudaFuncAttributeMaxDynamicSharedMemorySize, ATTN_SMEM);

    split_x_kernel<<<(MM * CC / 4 + 255) / 256, 256>>>(x);
    {
        dim3 blk(32, 8);
        transpose_split_kernel<<<dim3(N3 / 32, CC / 32), blk>>>(W_attn, 0);
        transpose_split_kernel<<<dim3(CC / 32, CC / 32), blk>>>(W_proj, 1);
    }
    qkv_mm<<<dim3(N3 / 128, MM / 128), 256, GEMM_SMEM>>>(b_attn);
    attn_mma<<<dim3(TT / 128, BB * HH), 256, ATTN_SMEM>>>();
    proj_mm<<<dim3(CC / 128, MM / 128), 256, GEMM_SMEM>>>(b_proj, out);
}